// round 1
// baseline (speedup 1.0000x reference)
#include <cuda_runtime.h>
#include <math.h>

// ---------------------------------------------------------------------------
// Problem constants
// ---------------------------------------------------------------------------
#define BATCH 16
#define NNODE 2048
#define R_TOTAL (BATCH * NNODE)   // 32768 (b,n) rows

// Scratch buffers (device globals: allocation-free)
__device__ float g_bufA[BATCH * NNODE * 20 * 64];  // 41,943,040 floats (max timeblock-64 out)
__device__ float g_bufB[BATCH * NNODE * 14 * 64];  // 29,360,128 floats (t5)
__device__ float g_bufC[BATCH * NNODE * 22 * 16];  // 11,534,336 floats (u = t @ theta)
__device__ float g_bufD[BATCH * NNODE * 22 * 16];  // 11,534,336 floats (relu(A @ u))

// ---------------------------------------------------------------------------
// Packed f32x2 helpers (sm_100+ FFMA2: 2x fp32 FMA throughput)
// ---------------------------------------------------------------------------
__device__ __forceinline__ unsigned long long pk2(float lo, float hi) {
    unsigned long long r;
    asm("mov.b64 %0, {%1, %2};" : "=l"(r) : "f"(lo), "f"(hi));
    return r;
}
__device__ __forceinline__ void fma2(unsigned long long& d, unsigned long long a,
                                     unsigned long long b) {
    asm("fma.rn.f32x2 %0, %1, %2, %0;" : "+l"(d) : "l"(a), "l"(b));
}
__device__ __forceinline__ float2 upk(unsigned long long v) {
    float lo, hi;
    asm("mov.b64 {%0, %1}, %2;" : "=f"(lo), "=f"(hi) : "l"(v));
    return make_float2(lo, hi);
}

// ---------------------------------------------------------------------------
// Gated temporal conv block (K=3): y = relu(sigmoid(conv_W2) * (conv_W0+conv_W1))
// conv_W0 + conv_W1 on the same X == one conv with (W0+W1), bias (b0+b1).
// If FUSE: emit u = y @ theta  (theta commutes with the A-aggregation).
//
// X: [R, TIN, CIN], W: [3,3,CIN,64], B3: [3,64], theta: [64,16]
// Y: FUSE ? [R, TOUT, 16] : [R, TOUT, 64]
// block: (64, 2) -> 2 rows per block; grid: R/2
// ---------------------------------------------------------------------------
template <int CIN, int TIN, bool FUSE>
__global__ __launch_bounds__(128) void timeblock_kernel(
    const float* __restrict__ X, const float* __restrict__ W,
    const float* __restrict__ B3, const float* __restrict__ theta,
    float* __restrict__ Y)
{
    constexpr int TOUT = TIN - 2;
    constexpr int ROWS = 2;
    __shared__ __align__(16) float Xs[ROWS * TIN * CIN];
    __shared__ __align__(16) float Ys[FUSE ? (ROWS * TOUT * 64) : 1];
    __shared__ __align__(16) float Ths[FUSE ? (64 * 16) : 1];

    const int co  = threadIdx.x;            // 0..63 output channel
    const int r   = threadIdx.y;            // row within block
    const int tid = r * 64 + co;
    const long row0 = (long)blockIdx.x * ROWS;

    // cooperative load of the 2 input rows (contiguous)
    for (int i = tid; i < ROWS * TIN * CIN; i += 128)
        Xs[i] = X[row0 * (TIN * CIN) + i];
    if (FUSE)
        for (int i = tid; i < 64 * 16; i += 128) Ths[i] = theta[i];
    __syncthreads();

    float acc_t[TOUT], acc_g[TOUT];
    const float bt = B3[co] + B3[64 + co];
    const float bg = B3[128 + co];
#pragma unroll
    for (int t = 0; t < TOUT; ++t) { acc_t[t] = bt; acc_g[t] = bg; }

    const float* Xr = &Xs[r * TIN * CIN];
#pragma unroll
    for (int k = 0; k < 3; ++k) {
        for (int cin = 0; cin < CIN; ++cin) {
            const float w0 = W[((0 * 3 + k) * CIN + cin) * 64 + co];
            const float w1 = W[((1 * 3 + k) * CIN + cin) * 64 + co];
            const float w2 = W[((2 * 3 + k) * CIN + cin) * 64 + co];
            const float wt = w0 + w1;
#pragma unroll
            for (int t = 0; t < TOUT; ++t) {
                const float xv = Xr[(t + k) * CIN + cin];
                acc_t[t] = fmaf(xv, wt, acc_t[t]);
                acc_g[t] = fmaf(xv, w2, acc_g[t]);
            }
        }
    }

#pragma unroll
    for (int t = 0; t < TOUT; ++t) {
        const float g = 1.0f / (1.0f + __expf(-acc_g[t]));
        float y = acc_t[t] * g;
        y = (y > 0.0f) ? y : 0.0f;
        if (FUSE)
            Ys[(r * TOUT + t) * 64 + co] = y;
        else
            Y[(row0 + r) * (long)(TOUT * 64) + t * 64 + co] = y;
    }

    if (FUSE) {
        __syncthreads();
        // u[rr, t, p] = sum_m Ys[rr, t, m] * theta[m, p]
        for (int o = tid; o < ROWS * TOUT * 16; o += 128) {
            const int p  = o & 15;
            const int t  = (o >> 4) % TOUT;
            const int rr = o / (16 * TOUT);
            float s = 0.0f;
#pragma unroll
            for (int m = 0; m < 64; ++m)
                s = fmaf(Ys[(rr * TOUT + t) * 64 + m], Ths[m * 16 + p], s);
            Y[(row0 + rr) * (long)(TOUT * 16) + t * 16 + p] = s;
        }
    }
}

// ---------------------------------------------------------------------------
// Batched GEMM with relu epilogue:  C[z] = relu(A @ U[z])
// A: [2048, 2048] row-major (shared across batch), U: [z][2048, F], C: [z][2048, F]
// Tiles: BM=64, BN=32, BK=16; 128 threads, 4x4 microtile, packed f32x2 FMA.
// F is a multiple of 32 (352 or 288) -> no bounds checks.
// ---------------------------------------------------------------------------
__global__ __launch_bounds__(128) void gemm_relu_kernel(
    const float* __restrict__ A, const float* __restrict__ U,
    float* __restrict__ C, int F)
{
    constexpr int BM = 64, BN = 32, BK = 16;
    __shared__ __align__(16) float As[BK][BM];  // transposed A tile
    __shared__ __align__(16) float Bs[BK][BN];

    const int tid = threadIdx.x;            // 0..127
    const int tx = tid & 7;                 // n dir: 8 * 4 = 32
    const int ty = tid >> 3;                // m dir: 16 * 4 = 64
    const int m0 = blockIdx.x * BM;
    const int n0 = blockIdx.y * BN;
    const float* Ub = U + (size_t)blockIdx.z * 2048 * F;
    float*       Cb = C + (size_t)blockIdx.z * 2048 * F;

    unsigned long long acc[4][2];
#pragma unroll
    for (int i = 0; i < 4; ++i) { acc[i][0] = 0ull; acc[i][1] = 0ull; }

    // A tile load indices: 2 float4 per thread (64x16 = 1024 floats / 128 thr)
    const int ar = tid >> 1;                // 0..63
    const int ac = (tid & 1) * 8;           // 0 or 8
    // B tile load: 1 float4 per thread (16x32 = 512 floats / 128 thr)
    const int br = tid >> 3;                // 0..15
    const int bc = (tid & 7) * 4;           // 0..28

    for (int k0 = 0; k0 < 2048; k0 += BK) {
        const float4 a0 = *(const float4*)&A[(size_t)(m0 + ar) * 2048 + k0 + ac];
        const float4 a1 = *(const float4*)&A[(size_t)(m0 + ar) * 2048 + k0 + ac + 4];
        const float4 bv = *(const float4*)&Ub[(size_t)(k0 + br) * F + n0 + bc];
        As[ac + 0][ar] = a0.x; As[ac + 1][ar] = a0.y;
        As[ac + 2][ar] = a0.z; As[ac + 3][ar] = a0.w;
        As[ac + 4][ar] = a1.x; As[ac + 5][ar] = a1.y;
        As[ac + 6][ar] = a1.z; As[ac + 7][ar] = a1.w;
        *(float4*)&Bs[br][bc] = bv;
        __syncthreads();

#pragma unroll
        for (int kk = 0; kk < BK; ++kk) {
            const float4 av = *(const float4*)&As[kk][ty * 4];
            const float4 b4 = *(const float4*)&Bs[kk][tx * 4];
            const unsigned long long b01 = pk2(b4.x, b4.y);
            const unsigned long long b23 = pk2(b4.z, b4.w);
            unsigned long long aa;
            aa = pk2(av.x, av.x); fma2(acc[0][0], aa, b01); fma2(acc[0][1], aa, b23);
            aa = pk2(av.y, av.y); fma2(acc[1][0], aa, b01); fma2(acc[1][1], aa, b23);
            aa = pk2(av.z, av.z); fma2(acc[2][0], aa, b01); fma2(acc[2][1], aa, b23);
            aa = pk2(av.w, av.w); fma2(acc[3][0], aa, b01); fma2(acc[3][1], aa, b23);
        }
        __syncthreads();
    }

#pragma unroll
    for (int i = 0; i < 4; ++i) {
        const float2 v0 = upk(acc[i][0]);
        const float2 v1 = upk(acc[i][1]);
        float4 o;
        o.x = v0.x > 0.0f ? v0.x : 0.0f;
        o.y = v0.y > 0.0f ? v0.y : 0.0f;
        o.z = v1.x > 0.0f ? v1.x : 0.0f;
        o.w = v1.y > 0.0f ? v1.y : 0.0f;
        *(float4*)&Cb[(size_t)(m0 + ty * 4 + i) * F + n0 + tx * 4] = o;
    }
}

// ---------------------------------------------------------------------------
// FC: out[row, p] = X[row, :896] @ W[896,12] + bias.  Warp per row.
// block: (32, 8)
// ---------------------------------------------------------------------------
__global__ __launch_bounds__(256) void fc_kernel(
    const float* __restrict__ X, const float* __restrict__ W,
    const float* __restrict__ bias, float* __restrict__ out)
{
    const int lane = threadIdx.x;
    const long row = (long)blockIdx.x * blockDim.y + threadIdx.y;
    const float* x = X + row * 896;
    float acc[12];
#pragma unroll
    for (int p = 0; p < 12; ++p) acc[p] = 0.0f;
    for (int e = lane; e < 896; e += 32) {
        const float xv = x[e];
#pragma unroll
        for (int p = 0; p < 12; ++p) acc[p] = fmaf(xv, W[e * 12 + p], acc[p]);
    }
#pragma unroll
    for (int off = 16; off > 0; off >>= 1) {
#pragma unroll
        for (int p = 0; p < 12; ++p)
            acc[p] += __shfl_down_sync(0xffffffffu, acc[p], off);
    }
    if (lane == 0) {
#pragma unroll
        for (int p = 0; p < 12; ++p) out[row * 12 + p] = acc[p] + bias[p];
    }
}

// ---------------------------------------------------------------------------
// Copy A_hat into the tail of the output (reference returns (out4, A_hat))
// ---------------------------------------------------------------------------
__global__ __launch_bounds__(256) void copy4_kernel(const float4* __restrict__ src,
                                                    float4* __restrict__ dst, int n4)
{
    const int i = blockIdx.x * blockDim.x + threadIdx.x;
    if (i < n4) dst[i] = src[i];
}

// ---------------------------------------------------------------------------
// kernel_launch
// ---------------------------------------------------------------------------
extern "C" void kernel_launch(void* const* d_in, const int* in_sizes, int n_in,
                              void* d_out, int out_size)
{
    const float* x       = (const float*)d_in[0];
    const float* A_hat   = (const float*)d_in[1];
    const float* tb1_w   = (const float*)d_in[2];
    const float* tb1_b   = (const float*)d_in[3];
    const float* theta1  = (const float*)d_in[4];
    const float* tb2_w   = (const float*)d_in[5];
    const float* tb2_b   = (const float*)d_in[6];
    const float* tb3_w   = (const float*)d_in[7];
    const float* tb3_b   = (const float*)d_in[8];
    const float* theta2  = (const float*)d_in[9];
    const float* tb4_w   = (const float*)d_in[10];
    const float* tb4_b   = (const float*)d_in[11];
    const float* tb5_w   = (const float*)d_in[12];
    const float* tb5_b   = (const float*)d_in[13];
    const float* fully_w = (const float*)d_in[14];
    const float* fully_b = (const float*)d_in[15];
    float* out = (float*)d_out;

    float *bufA, *bufB, *bufC, *bufD;
    cudaGetSymbolAddress((void**)&bufA, g_bufA);
    cudaGetSymbolAddress((void**)&bufB, g_bufB);
    cudaGetSymbolAddress((void**)&bufC, g_bufC);
    cudaGetSymbolAddress((void**)&bufD, g_bufD);

    const dim3 tbBlock(64, 2);
    const int  tbGrid = R_TOTAL / 2;

    // ---- block 1 ----
    // timeblock1 (Cin=2, T 24->22) fused with theta1 -> u1 [R,22,16]
    timeblock_kernel<2, 24, true><<<tbGrid, tbBlock>>>(x, tb1_w, tb1_b, theta1, bufC);
    // t2 = relu(A @ u1) -> [R,22,16]   (F = 22*16 = 352)
    gemm_relu_kernel<<<dim3(32, 352 / 32, BATCH), 128>>>(A_hat, bufC, bufD, 352);
    // timeblock2 (Cin=16, T 22->20) -> out1 [R,20,64]
    timeblock_kernel<16, 22, false><<<tbGrid, tbBlock>>>(bufD, tb2_w, tb2_b, nullptr, bufA);

    // ---- block 2 ----
    // timeblock3 (Cin=64, T 20->18) fused with theta2 -> u2 [R,18,16]
    timeblock_kernel<64, 20, true><<<tbGrid, tbBlock>>>(bufA, tb3_w, tb3_b, theta2, bufC);
    // t4 = relu(A @ u2) -> [R,18,16]   (F = 18*16 = 288)
    gemm_relu_kernel<<<dim3(32, 288 / 32, BATCH), 128>>>(A_hat, bufC, bufD, 288);
    // timeblock4 (Cin=16, T 18->16) -> out2 [R,16,64]
    timeblock_kernel<16, 18, false><<<tbGrid, tbBlock>>>(bufD, tb4_w, tb4_b, nullptr, bufA);

    // ---- head ----
    // timeblock5 (Cin=64, T 16->14) -> out3 [R,14,64]
    timeblock_kernel<64, 16, false><<<tbGrid, tbBlock>>>(bufA, tb5_w, tb5_b, nullptr, bufB);
    // FC: [R, 896] @ [896, 12] + b -> out4 [R, 12]
    fc_kernel<<<R_TOTAL / 8, dim3(32, 8)>>>(bufB, fully_w, fully_b, out);

    // A_hat passthrough into output tail
    const int n4 = (NNODE * NNODE) / 4;
    copy4_kernel<<<(n4 + 255) / 256, 256>>>((const float4*)A_hat,
                                            (float4*)(out + (long)R_TOTAL * 12), n4);
}

// round 2
// speedup vs baseline: 1.0010x; 1.0010x over previous
#include <cuda_runtime.h>
#include <math.h>

// ---------------------------------------------------------------------------
// Problem constants
// ---------------------------------------------------------------------------
#define BATCH 16
#define NNODE 2048
#define R_TOTAL (BATCH * NNODE)   // 32768 (b,n) rows

// Scratch buffers (device globals: allocation-free)
__device__ float g_bufA[BATCH * NNODE * 20 * 64];  // 41,943,040 floats (max timeblock-64 out)
__device__ float g_bufB[BATCH * NNODE * 14 * 64];  // 29,360,128 floats (t5)
__device__ float g_bufC[BATCH * NNODE * 22 * 16];  // 11,534,336 floats (u = t @ theta)
__device__ float g_bufD[BATCH * NNODE * 22 * 16];  // 11,534,336 floats (relu(A @ u))

// ---------------------------------------------------------------------------
// Packed f32x2 helpers (sm_100+ FFMA2: 2x fp32 FMA throughput)
// ---------------------------------------------------------------------------
__device__ __forceinline__ unsigned long long pk2(float lo, float hi) {
    unsigned long long r;
    asm("mov.b64 %0, {%1, %2};" : "=l"(r) : "f"(lo), "f"(hi));
    return r;
}
__device__ __forceinline__ void fma2(unsigned long long& d, unsigned long long a,
                                     unsigned long long b) {
    asm("fma.rn.f32x2 %0, %1, %2, %0;" : "+l"(d) : "l"(a), "l"(b));
}
__device__ __forceinline__ float2 upk(unsigned long long v) {
    float lo, hi;
    asm("mov.b64 {%0, %1}, %2;" : "=f"(lo), "=f"(hi) : "l"(v));
    return make_float2(lo, hi);
}

// ---------------------------------------------------------------------------
// Gated temporal conv block (K=3): y = relu(sigmoid(conv_W2) * (conv_W0+conv_W1))
// conv_W0 + conv_W1 on the same X == one conv with (W0+W1), bias (b0+b1).
// If FUSE: emit u = y @ theta  (theta commutes with the A-aggregation).
//
// X: [R, TIN, CIN], W: [3,3,CIN,64], B3: [3,64], theta: [64,16]
// Y: FUSE ? [R, TOUT, 16] : [R, TOUT, 64]
// block: (64, 2) -> 2 rows per block; grid: R/2
// ---------------------------------------------------------------------------
template <int CIN, int TIN, bool FUSE>
__global__ __launch_bounds__(128) void timeblock_kernel(
    const float* __restrict__ X, const float* __restrict__ W,
    const float* __restrict__ B3, const float* __restrict__ theta,
    float* __restrict__ Y)
{
    constexpr int TOUT = TIN - 2;
    constexpr int ROWS = 2;
    __shared__ __align__(16) float Xs[ROWS * TIN * CIN];
    __shared__ __align__(16) float Ys[FUSE ? (ROWS * TOUT * 64) : 1];
    __shared__ __align__(16) float Ths[FUSE ? (64 * 16) : 1];

    const int co  = threadIdx.x;            // 0..63 output channel
    const int r   = threadIdx.y;            // row within block
    const int tid = r * 64 + co;
    const long row0 = (long)blockIdx.x * ROWS;

    // cooperative load of the 2 input rows (contiguous)
    for (int i = tid; i < ROWS * TIN * CIN; i += 128)
        Xs[i] = X[row0 * (TIN * CIN) + i];
    if (FUSE)
        for (int i = tid; i < 64 * 16; i += 128) Ths[i] = theta[i];
    __syncthreads();

    float acc_t[TOUT], acc_g[TOUT];
    const float bt = B3[co] + B3[64 + co];
    const float bg = B3[128 + co];
#pragma unroll
    for (int t = 0; t < TOUT; ++t) { acc_t[t] = bt; acc_g[t] = bg; }

    const float* Xr = &Xs[r * TIN * CIN];
#pragma unroll
    for (int k = 0; k < 3; ++k) {
        for (int cin = 0; cin < CIN; ++cin) {
            const float w0 = W[((0 * 3 + k) * CIN + cin) * 64 + co];
            const float w1 = W[((1 * 3 + k) * CIN + cin) * 64 + co];
            const float w2 = W[((2 * 3 + k) * CIN + cin) * 64 + co];
            const float wt = w0 + w1;
#pragma unroll
            for (int t = 0; t < TOUT; ++t) {
                const float xv = Xr[(t + k) * CIN + cin];
                acc_t[t] = fmaf(xv, wt, acc_t[t]);
                acc_g[t] = fmaf(xv, w2, acc_g[t]);
            }
        }
    }

#pragma unroll
    for (int t = 0; t < TOUT; ++t) {
        const float g = 1.0f / (1.0f + __expf(-acc_g[t]));
        float y = acc_t[t] * g;
        y = (y > 0.0f) ? y : 0.0f;
        if (FUSE)
            Ys[(r * TOUT + t) * 64 + co] = y;
        else
            Y[(row0 + r) * (long)(TOUT * 64) + t * 64 + co] = y;
    }

    if (FUSE) {
        __syncthreads();
        // u[rr, t, p] = sum_m Ys[rr, t, m] * theta[m, p]
        for (int o = tid; o < ROWS * TOUT * 16; o += 128) {
            const int p  = o & 15;
            const int t  = (o >> 4) % TOUT;
            const int rr = o / (16 * TOUT);
            float s = 0.0f;
#pragma unroll
            for (int m = 0; m < 64; ++m)
                s = fmaf(Ys[(rr * TOUT + t) * 64 + m], Ths[m * 16 + p], s);
            Y[(row0 + rr) * (long)(TOUT * 16) + t * 16 + p] = s;
        }
    }
}

// ---------------------------------------------------------------------------
// Batched GEMM with relu epilogue:  C[z] = relu(A @ U[z])
// A: [2048, 2048] row-major (shared across batch), U: [z][2048, F], C: [z][2048, F]
// Tiles: BM=64, BN=32, BK=16; 128 threads, 4x4 microtile, packed f32x2 FMA.
// F is a multiple of 32 (352 or 288) -> no bounds checks.
// ---------------------------------------------------------------------------
__global__ __launch_bounds__(128) void gemm_relu_kernel(
    const float* __restrict__ A, const float* __restrict__ U,
    float* __restrict__ C, int F)
{
    constexpr int BM = 64, BN = 32, BK = 16;
    __shared__ __align__(16) float As[BK][BM];  // transposed A tile
    __shared__ __align__(16) float Bs[BK][BN];

    const int tid = threadIdx.x;            // 0..127
    const int tx = tid & 7;                 // n dir: 8 * 4 = 32
    const int ty = tid >> 3;                // m dir: 16 * 4 = 64
    const int m0 = blockIdx.x * BM;
    const int n0 = blockIdx.y * BN;
    const float* Ub = U + (size_t)blockIdx.z * 2048 * F;
    float*       Cb = C + (size_t)blockIdx.z * 2048 * F;

    unsigned long long acc[4][2];
#pragma unroll
    for (int i = 0; i < 4; ++i) { acc[i][0] = 0ull; acc[i][1] = 0ull; }

    // A tile load indices: 2 float4 per thread (64x16 = 1024 floats / 128 thr)
    const int ar = tid >> 1;                // 0..63
    const int ac = (tid & 1) * 8;           // 0 or 8
    // B tile load: 1 float4 per thread (16x32 = 512 floats / 128 thr)
    const int br = tid >> 3;                // 0..15
    const int bc = (tid & 7) * 4;           // 0..28

    for (int k0 = 0; k0 < 2048; k0 += BK) {
        const float4 a0 = *(const float4*)&A[(size_t)(m0 + ar) * 2048 + k0 + ac];
        const float4 a1 = *(const float4*)&A[(size_t)(m0 + ar) * 2048 + k0 + ac + 4];
        const float4 bv = *(const float4*)&Ub[(size_t)(k0 + br) * F + n0 + bc];
        As[ac + 0][ar] = a0.x; As[ac + 1][ar] = a0.y;
        As[ac + 2][ar] = a0.z; As[ac + 3][ar] = a0.w;
        As[ac + 4][ar] = a1.x; As[ac + 5][ar] = a1.y;
        As[ac + 6][ar] = a1.z; As[ac + 7][ar] = a1.w;
        *(float4*)&Bs[br][bc] = bv;
        __syncthreads();

#pragma unroll
        for (int kk = 0; kk < BK; ++kk) {
            const float4 av = *(const float4*)&As[kk][ty * 4];
            const float4 b4 = *(const float4*)&Bs[kk][tx * 4];
            const unsigned long long b01 = pk2(b4.x, b4.y);
            const unsigned long long b23 = pk2(b4.z, b4.w);
            unsigned long long aa;
            aa = pk2(av.x, av.x); fma2(acc[0][0], aa, b01); fma2(acc[0][1], aa, b23);
            aa = pk2(av.y, av.y); fma2(acc[1][0], aa, b01); fma2(acc[1][1], aa, b23);
            aa = pk2(av.z, av.z); fma2(acc[2][0], aa, b01); fma2(acc[2][1], aa, b23);
            aa = pk2(av.w, av.w); fma2(acc[3][0], aa, b01); fma2(acc[3][1], aa, b23);
        }
        __syncthreads();
    }

#pragma unroll
    for (int i = 0; i < 4; ++i) {
        const float2 v0 = upk(acc[i][0]);
        const float2 v1 = upk(acc[i][1]);
        float4 o;
        o.x = v0.x > 0.0f ? v0.x : 0.0f;
        o.y = v0.y > 0.0f ? v0.y : 0.0f;
        o.z = v1.x > 0.0f ? v1.x : 0.0f;
        o.w = v1.y > 0.0f ? v1.y : 0.0f;
        *(float4*)&Cb[(size_t)(m0 + ty * 4 + i) * F + n0 + tx * 4] = o;
    }
}

// ---------------------------------------------------------------------------
// FC: out[row, p] = X[row, :896] @ W[896,12] + bias.  Warp per row.
// block: (32, 8)
// ---------------------------------------------------------------------------
__global__ __launch_bounds__(256) void fc_kernel(
    const float* __restrict__ X, const float* __restrict__ W,
    const float* __restrict__ bias, float* __restrict__ out)
{
    const int lane = threadIdx.x;
    const long row = (long)blockIdx.x * blockDim.y + threadIdx.y;
    const float* x = X + row * 896;
    float acc[12];
#pragma unroll
    for (int p = 0; p < 12; ++p) acc[p] = 0.0f;
    for (int e = lane; e < 896; e += 32) {
        const float xv = x[e];
#pragma unroll
        for (int p = 0; p < 12; ++p) acc[p] = fmaf(xv, W[e * 12 + p], acc[p]);
    }
#pragma unroll
    for (int off = 16; off > 0; off >>= 1) {
#pragma unroll
        for (int p = 0; p < 12; ++p)
            acc[p] += __shfl_down_sync(0xffffffffu, acc[p], off);
    }
    if (lane == 0) {
#pragma unroll
        for (int p = 0; p < 12; ++p) out[row * 12 + p] = acc[p] + bias[p];
    }
}

// ---------------------------------------------------------------------------
// Copy A_hat into the tail of the output (reference returns (out4, A_hat))
// ---------------------------------------------------------------------------
__global__ __launch_bounds__(256) void copy4_kernel(const float4* __restrict__ src,
                                                    float4* __restrict__ dst, int n4)
{
    const int i = blockIdx.x * blockDim.x + threadIdx.x;
    if (i < n4) dst[i] = src[i];
}

// ---------------------------------------------------------------------------
// kernel_launch
// ---------------------------------------------------------------------------
extern "C" void kernel_launch(void* const* d_in, const int* in_sizes, int n_in,
                              void* d_out, int out_size)
{
    const float* x       = (const float*)d_in[0];
    const float* A_hat   = (const float*)d_in[1];
    const float* tb1_w   = (const float*)d_in[2];
    const float* tb1_b   = (const float*)d_in[3];
    const float* theta1  = (const float*)d_in[4];
    const float* tb2_w   = (const float*)d_in[5];
    const float* tb2_b   = (const float*)d_in[6];
    const float* tb3_w   = (const float*)d_in[7];
    const float* tb3_b   = (const float*)d_in[8];
    const float* theta2  = (const float*)d_in[9];
    const float* tb4_w   = (const float*)d_in[10];
    const float* tb4_b   = (const float*)d_in[11];
    const float* tb5_w   = (const float*)d_in[12];
    const float* tb5_b   = (const float*)d_in[13];
    const float* fully_w = (const float*)d_in[14];
    const float* fully_b = (const float*)d_in[15];
    float* out = (float*)d_out;

    float *bufA, *bufB, *bufC, *bufD;
    cudaGetSymbolAddress((void**)&bufA, g_bufA);
    cudaGetSymbolAddress((void**)&bufB, g_bufB);
    cudaGetSymbolAddress((void**)&bufC, g_bufC);
    cudaGetSymbolAddress((void**)&bufD, g_bufD);

    const dim3 tbBlock(64, 2);
    const int  tbGrid = R_TOTAL / 2;

    // ---- block 1 ----
    // timeblock1 (Cin=2, T 24->22) fused with theta1 -> u1 [R,22,16]
    timeblock_kernel<2, 24, true><<<tbGrid, tbBlock>>>(x, tb1_w, tb1_b, theta1, bufC);
    // t2 = relu(A @ u1) -> [R,22,16]   (F = 22*16 = 352)
    gemm_relu_kernel<<<dim3(32, 352 / 32, BATCH), 128>>>(A_hat, bufC, bufD, 352);
    // timeblock2 (Cin=16, T 22->20) -> out1 [R,20,64]
    timeblock_kernel<16, 22, false><<<tbGrid, tbBlock>>>(bufD, tb2_w, tb2_b, nullptr, bufA);

    // ---- block 2 ----
    // timeblock3 (Cin=64, T 20->18) fused with theta2 -> u2 [R,18,16]
    timeblock_kernel<64, 20, true><<<tbGrid, tbBlock>>>(bufA, tb3_w, tb3_b, theta2, bufC);
    // t4 = relu(A @ u2) -> [R,18,16]   (F = 18*16 = 288)
    gemm_relu_kernel<<<dim3(32, 288 / 32, BATCH), 128>>>(A_hat, bufC, bufD, 288);
    // timeblock4 (Cin=16, T 18->16) -> out2 [R,16,64]
    timeblock_kernel<16, 18, false><<<tbGrid, tbBlock>>>(bufD, tb4_w, tb4_b, nullptr, bufA);

    // ---- head ----
    // timeblock5 (Cin=64, T 16->14) -> out3 [R,14,64]
    timeblock_kernel<64, 16, false><<<tbGrid, tbBlock>>>(bufA, tb5_w, tb5_b, nullptr, bufB);
    // FC: [R, 896] @ [896, 12] + b -> out4 [R, 12]
    fc_kernel<<<R_TOTAL / 8, dim3(32, 8)>>>(bufB, fully_w, fully_b, out);

    // A_hat passthrough into output tail
    const int n4 = (NNODE * NNODE) / 4;
    copy4_kernel<<<(n4 + 255) / 256, 256>>>((const float4*)A_hat,
                                            (float4*)(out + (long)R_TOTAL * 12), n4);
}

// round 4
// speedup vs baseline: 2.0247x; 2.0227x over previous
#include <cuda_runtime.h>
#include <cuda_bf16.h>
#include <cstdint>
#include <math.h>

#define BATCH 16
#define NNODE 2048
#define R_TOTAL (BATCH * NNODE)

// ---------------- scratch (device globals) ----------------
__device__ __align__(16) float g_bufA[R_TOTAL * 20 * 64];
__device__ __align__(16) float g_bufB[R_TOTAL * 14 * 64];
__device__ __align__(16) float g_bufC[R_TOTAL * 22 * 16];
__device__ __align__(16) float g_bufD[R_TOTAL * 22 * 16];
__device__ __align__(16) __nv_bfloat16 g_Ahi[NNODE * NNODE];
__device__ __align__(16) __nv_bfloat16 g_Alo[NNODE * NNODE];
__device__ __align__(16) __nv_bfloat16 g_Uhi[(size_t)BATCH * 352 * NNODE];
__device__ __align__(16) __nv_bfloat16 g_Ulo[(size_t)BATCH * 352 * NNODE];
__device__ __align__(16) float2 g_Wp[5][3 * 64 * 64];
__device__ __align__(16) float2 g_bp[5][64];

// ---------------- f32x2 helpers ----------------
__device__ __forceinline__ unsigned long long pk2(float lo, float hi) {
    unsigned long long r;
    asm("mov.b64 %0, {%1, %2};" : "=l"(r) : "f"(lo), "f"(hi));
    return r;
}
__device__ __forceinline__ void fma2(unsigned long long& d, unsigned long long a,
                                     unsigned long long b) {
    asm("fma.rn.f32x2 %0, %1, %2, %0;" : "+l"(d) : "l"(a), "l"(b));
}
__device__ __forceinline__ float2 upk(unsigned long long v) {
    float lo, hi;
    asm("mov.b64 {%0, %1}, %2;" : "=f"(lo), "=f"(hi) : "l"(v));
    return make_float2(lo, hi);
}

// ---------------- mma / cp.async helpers (baseline PTX, no arch-specific) --
__device__ __forceinline__ uint32_t smem_u32(const void* p) {
    uint32_t a;
    asm("{ .reg .u64 t; cvta.to.shared.u64 t, %1; cvt.u32.u64 %0, t; }" : "=r"(a) : "l"(p));
    return a;
}
#define CP16(sa, gp) asm volatile("cp.async.ca.shared.global [%0], [%1], 16;" \
    :: "r"(sa), "l"(gp) : "memory")
#define CPCOMMIT() asm volatile("cp.async.commit_group;" ::: "memory")
#define CPWAIT1()  asm volatile("cp.async.wait_group 1;" ::: "memory")
#define CPWAIT0()  asm volatile("cp.async.wait_group 0;" ::: "memory")
#define LDSM4(r, a) asm volatile( \
    "ldmatrix.sync.aligned.m8n8.x4.shared.b16 {%0,%1,%2,%3}, [%4];" \
    : "=r"((r)[0]), "=r"((r)[1]), "=r"((r)[2]), "=r"((r)[3]) : "r"(a))
__device__ __forceinline__ void mma_bf16(float* c, const uint32_t* a,
                                         uint32_t b0, uint32_t b1) {
    asm volatile(
        "mma.sync.aligned.m16n8k16.row.col.f32.bf16.bf16.f32 "
        "{%0,%1,%2,%3}, {%4,%5,%6,%7}, {%8,%9}, {%0,%1,%2,%3};"
        : "+f"(c[0]), "+f"(c[1]), "+f"(c[2]), "+f"(c[3])
        : "r"(a[0]), "r"(a[1]), "r"(a[2]), "r"(a[3]), "r"(b0), "r"(b1));
}

// ---------------- prep kernels ----------------
__global__ __launch_bounds__(256) void packW_kernel(const float* __restrict__ W,
    const float* __restrict__ B3, float2* __restrict__ Wp, float2* __restrict__ bp, int n)
{
    int i = blockIdx.x * 256 + threadIdx.x;
    if (i < n) Wp[i] = make_float2(W[i] + W[n + i], W[2 * n + i]);
    if (i < 64) bp[i] = make_float2(B3[i] + B3[64 + i], B3[128 + i]);
}

__global__ __launch_bounds__(256) void splitA_kernel(const float* __restrict__ A,
    __nv_bfloat16* __restrict__ hi, __nv_bfloat16* __restrict__ lo)
{
    int i = blockIdx.x * 256 + threadIdx.x;
    float a = A[i];
    __nv_bfloat16 h = __float2bfloat16(a);
    hi[i] = h;
    lo[i] = __float2bfloat16(a - __bfloat162float(h));
}

// U [z][2048][F] -> Ut hi/lo [z][F][2048] bf16 split
template <int F>
__global__ __launch_bounds__(256) void tsplitU_kernel(const float* __restrict__ U,
    __nv_bfloat16* __restrict__ th, __nv_bfloat16* __restrict__ tl)
{
    __shared__ float t[32][33];
    const int j0 = blockIdx.x * 32, f0 = blockIdx.y * 32, z = blockIdx.z;
    const int tx = threadIdx.x & 31, ty = threadIdx.x >> 5;
#pragma unroll
    for (int q = 0; q < 32; q += 8)
        t[ty + q][tx] = U[((size_t)z * 2048 + j0 + ty + q) * F + f0 + tx];
    __syncthreads();
#pragma unroll
    for (int q = 0; q < 32; q += 8) {
        float v = t[tx][ty + q];
        __nv_bfloat16 h = __float2bfloat16(v);
        size_t o = ((size_t)z * F + f0 + ty + q) * 2048 + j0 + tx;
        th[o] = h;
        tl[o] = __float2bfloat16(v - __bfloat162float(h));
    }
}

// ---------------- timeblock ----------------
template <int CIN, int TIN, bool FUSE>
__global__ __launch_bounds__(128) void timeblock_kernel(
    const float* __restrict__ X, const float2* __restrict__ Wp,
    const float2* __restrict__ bp, const float* __restrict__ theta,
    float* __restrict__ Y)
{
    constexpr int TOUT = TIN - 2;
    constexpr int ROWS = 2;
    __shared__ __align__(16) float Xs[ROWS * TIN * CIN];
    __shared__ __align__(16) float Ys[FUSE ? (ROWS * TOUT * 64) : 1];
    __shared__ __align__(16) float Ths[FUSE ? (64 * 16) : 1];

    const int co = threadIdx.x, r = threadIdx.y;
    const int tid = r * 64 + co;
    const long row0 = (long)blockIdx.x * ROWS;

    {
        const float4* src = (const float4*)(X + row0 * (TIN * CIN));
        float4* dst = (float4*)Xs;
        for (int i = tid; i < ROWS * TIN * CIN / 4; i += 128) dst[i] = src[i];
    }
    if (FUSE)
        for (int i = tid; i < 64 * 16; i += 128) Ths[i] = theta[i];
    __syncthreads();

    const float2 bb = bp[co];
    unsigned long long acc2[TOUT];
#pragma unroll
    for (int t = 0; t < TOUT; ++t) acc2[t] = pk2(bb.x, bb.y);

    const float* Xr = &Xs[r * TIN * CIN];
    for (int cin = 0; cin < CIN; ++cin) {
        unsigned long long xp[TIN];
#pragma unroll
        for (int t = 0; t < TIN; ++t) {
            const float v = Xr[t * CIN + cin];
            xp[t] = pk2(v, v);
        }
#pragma unroll
        for (int k = 0; k < 3; ++k) {
            const float2 wv = Wp[(k * CIN + cin) * 64 + co];
            const unsigned long long wp = pk2(wv.x, wv.y);
#pragma unroll
            for (int t = 0; t < TOUT; ++t) fma2(acc2[t], xp[t + k], wp);
        }
    }

#pragma unroll
    for (int t = 0; t < TOUT; ++t) {
        const float2 a = upk(acc2[t]);
        const float g = 1.0f / (1.0f + __expf(-a.y));
        float y = a.x * g;
        y = (y > 0.0f) ? y : 0.0f;
        if (FUSE) Ys[(r * TOUT + t) * 64 + co] = y;
        else Y[(row0 + r) * (long)(TOUT * 64) + t * 64 + co] = y;
    }

    if (FUSE) {
        __syncthreads();
        for (int o = tid; o < ROWS * TOUT * 16; o += 128) {
            const int p = o & 15, t = (o >> 4) % TOUT, rr = o / (16 * TOUT);
            float s = 0.0f;
#pragma unroll
            for (int m = 0; m < 64; ++m)
                s = fmaf(Ys[(rr * TOUT + t) * 64 + m], Ths[m * 16 + p], s);
            Y[(row0 + rr) * (long)(TOUT * 16) + t * 16 + p] = s;
        }
    }
}

// ---------------- tensor-core GEMM: C[z] = relu(A @ U[z]) -------------------
// A hi/lo bf16 [2048,2048] row-major; Ut hi/lo [z][F][2048]; C [z][2048][F].
// 3-term bf16 split via mma.sync m16n8k16. BM=128, BN=32, BK=32, 256 thr.
template <int F>
__global__ __launch_bounds__(256) void gemm_mma_kernel(
    const __nv_bfloat16* __restrict__ Ahi, const __nv_bfloat16* __restrict__ Alo,
    const __nv_bfloat16* __restrict__ Uhi, const __nv_bfloat16* __restrict__ Ulo,
    float* __restrict__ C)
{
    // smem rows padded to 80B (32 bf16 data + 16B pad): conflict-free ldmatrix
    constexpr uint32_t ALOFF = 128 * 80;          // 10240
    constexpr uint32_t BHOFF = 2 * 128 * 80;      // 20480
    constexpr uint32_t BLOFF = BHOFF + 32 * 80;   // 23040
    constexpr uint32_t STG   = BLOFF + 32 * 80;   // 25600 bytes per stage
    extern __shared__ __align__(128) char smc[];
    const uint32_t sb = smem_u32(smc);

    const int tid = threadIdx.x, w = tid >> 5, lane = tid & 31;
    const int m0 = blockIdx.x * 128, n0 = blockIdx.y * 32, z = blockIdx.z;

    const __nv_bfloat16* Ah = Ahi + (size_t)m0 * 2048;
    const __nv_bfloat16* Al = Alo + (size_t)m0 * 2048;
    const __nv_bfloat16* Bh = Uhi + ((size_t)z * F + n0) * 2048;
    const __nv_bfloat16* Bl = Ulo + ((size_t)z * F + n0) * 2048;

    // loader indices
    const int ra = tid >> 2;                 // 0..63 (A row, +64 for second half)
    const uint32_t cb = (tid & 3) * 16;      // byte col within row
    const int ce = (tid & 3) * 8;            // element col
    const int rb = (tid & 127) >> 2;         // 0..31 (B row)
    const uint32_t cbB = ((tid & 127) & 3) * 16;
    const int ceB = ((tid & 127) & 3) * 8;
    const __nv_bfloat16* Bt = (tid < 128) ? Bh : Bl;
    const uint32_t boff = (tid < 128) ? BHOFF : BLOFF;

#define LOAD_STAGE(buf, k0) do {                                               \
    const uint32_t st_ = sb + (buf) * STG;                                     \
    CP16(st_ + ra * 80 + cb,               Ah + (size_t)ra * 2048 + (k0) + ce);\
    CP16(st_ + (ra + 64) * 80 + cb,        Ah + (size_t)(ra + 64) * 2048 + (k0) + ce);\
    CP16(st_ + ALOFF + ra * 80 + cb,       Al + (size_t)ra * 2048 + (k0) + ce);\
    CP16(st_ + ALOFF + (ra + 64) * 80 + cb,Al + (size_t)(ra + 64) * 2048 + (k0) + ce);\
    CP16(st_ + boff + rb * 80 + cbB,       Bt + (size_t)rb * 2048 + (k0) + ceB);\
    CPCOMMIT();                                                                \
} while (0)

    float acc[4][4];
#pragma unroll
    for (int i = 0; i < 4; ++i)
#pragma unroll
        for (int j = 0; j < 4; ++j) acc[i][j] = 0.0f;

    LOAD_STAGE(0, 0);

    // per-warp ldmatrix base offsets
    const uint32_t aoff = (uint32_t)((w * 16 + (lane & 15)) * 80 + (lane >> 4) * 16);
    const uint32_t boff2 = (uint32_t)((lane & 7) * 80 + (lane >> 3) * 16);

    for (int it = 0; it < 64; ++it) {
        if (it < 63) {
            LOAD_STAGE((it + 1) & 1, (it + 1) * 32);
            CPWAIT1();
        } else {
            CPWAIT0();
        }
        __syncthreads();

        const uint32_t st = sb + (it & 1) * STG;
        uint32_t aF[2][2][4];   // [term][kstep][4]
        uint32_t bF[2][4][4];   // [term][ntile][4]
        LDSM4(aF[0][0], st + aoff);
        LDSM4(aF[0][1], st + aoff + 32);
        LDSM4(aF[1][0], st + ALOFF + aoff);
        LDSM4(aF[1][1], st + ALOFF + aoff + 32);
#pragma unroll
        for (int nt = 0; nt < 4; ++nt) {
            LDSM4(bF[0][nt], st + BHOFF + boff2 + nt * 8 * 80);
            LDSM4(bF[1][nt], st + BLOFF + boff2 + nt * 8 * 80);
        }
#pragma unroll
        for (int ks = 0; ks < 2; ++ks)
#pragma unroll
            for (int nt = 0; nt < 4; ++nt) {
                mma_bf16(acc[nt], aF[0][ks], bF[0][nt][2 * ks], bF[0][nt][2 * ks + 1]);
                mma_bf16(acc[nt], aF[0][ks], bF[1][nt][2 * ks], bF[1][nt][2 * ks + 1]);
                mma_bf16(acc[nt], aF[1][ks], bF[0][nt][2 * ks], bF[0][nt][2 * ks + 1]);
            }
        __syncthreads();
    }

    // epilogue: relu + store
    const int mr = m0 + w * 16 + (lane >> 2);
    const int cc = n0 + 2 * (lane & 3);
    float* C0 = C + ((size_t)z * 2048 + mr) * F + cc;
    float* C1 = C + ((size_t)z * 2048 + mr + 8) * F + cc;
#pragma unroll
    for (int nt = 0; nt < 4; ++nt) {
        float2 v0 = make_float2(fmaxf(acc[nt][0], 0.0f), fmaxf(acc[nt][1], 0.0f));
        float2 v1 = make_float2(fmaxf(acc[nt][2], 0.0f), fmaxf(acc[nt][3], 0.0f));
        *(float2*)(C0 + nt * 8) = v0;
        *(float2*)(C1 + nt * 8) = v1;
    }
#undef LOAD_STAGE
}

// ---------------- FC + copy ----------------
__global__ __launch_bounds__(256) void fc_kernel(const float* __restrict__ X,
    const float* __restrict__ W, const float* __restrict__ bias, float* __restrict__ out)
{
    const int lane = threadIdx.x;
    const long row = (long)blockIdx.x * blockDim.y + threadIdx.y;
    const float* x = X + row * 896;
    float acc[12];
#pragma unroll
    for (int p = 0; p < 12; ++p) acc[p] = 0.0f;
    for (int e = lane; e < 896; e += 32) {
        const float xv = x[e];
#pragma unroll
        for (int p = 0; p < 12; ++p) acc[p] = fmaf(xv, W[e * 12 + p], acc[p]);
    }
#pragma unroll
    for (int off = 16; off > 0; off >>= 1)
#pragma unroll
        for (int p = 0; p < 12; ++p) acc[p] += __shfl_down_sync(0xffffffffu, acc[p], off);
    if (lane == 0)
#pragma unroll
        for (int p = 0; p < 12; ++p) out[row * 12 + p] = acc[p] + bias[p];
}

__global__ __launch_bounds__(256) void copy4_kernel(const float4* __restrict__ s,
                                                    float4* __restrict__ d, int n4)
{
    const int i = blockIdx.x * blockDim.x + threadIdx.x;
    if (i < n4) d[i] = s[i];
}

// ---------------- launch ----------------
extern "C" void kernel_launch(void* const* d_in, const int* in_sizes, int n_in,
                              void* d_out, int out_size)
{
    const float* x       = (const float*)d_in[0];
    const float* A_hat   = (const float*)d_in[1];
    const float* tb1_w   = (const float*)d_in[2];
    const float* tb1_b   = (const float*)d_in[3];
    const float* theta1  = (const float*)d_in[4];
    const float* tb2_w   = (const float*)d_in[5];
    const float* tb2_b   = (const float*)d_in[6];
    const float* tb3_w   = (const float*)d_in[7];
    const float* tb3_b   = (const float*)d_in[8];
    const float* theta2  = (const float*)d_in[9];
    const float* tb4_w   = (const float*)d_in[10];
    const float* tb4_b   = (const float*)d_in[11];
    const float* tb5_w   = (const float*)d_in[12];
    const float* tb5_b   = (const float*)d_in[13];
    const float* fully_w = (const float*)d_in[14];
    const float* fully_b = (const float*)d_in[15];
    float* out = (float*)d_out;

    float *bufA, *bufB, *bufC, *bufD;
    __nv_bfloat16 *Ahi, *Alo, *Uhi, *Ulo;
    float2 *Wp, *bp;
    cudaGetSymbolAddress((void**)&bufA, g_bufA);
    cudaGetSymbolAddress((void**)&bufB, g_bufB);
    cudaGetSymbolAddress((void**)&bufC, g_bufC);
    cudaGetSymbolAddress((void**)&bufD, g_bufD);
    cudaGetSymbolAddress((void**)&Ahi, g_Ahi);
    cudaGetSymbolAddress((void**)&Alo, g_Alo);
    cudaGetSymbolAddress((void**)&Uhi, g_Uhi);
    cudaGetSymbolAddress((void**)&Ulo, g_Ulo);
    cudaGetSymbolAddress((void**)&Wp, g_Wp);
    cudaGetSymbolAddress((void**)&bp, g_bp);

    constexpr int WPSTRIDE = 3 * 64 * 64;
    constexpr int SMEM_G = 2 * 25600;   // 51200 bytes
    cudaFuncSetAttribute(gemm_mma_kernel<352>,
                         cudaFuncAttributeMaxDynamicSharedMemorySize, SMEM_G);
    cudaFuncSetAttribute(gemm_mma_kernel<288>,
                         cudaFuncAttributeMaxDynamicSharedMemorySize, SMEM_G);

    // prep
    packW_kernel<<<2, 256>>>(tb1_w, tb1_b, Wp + 0 * WPSTRIDE, bp + 0 * 64, 3 * 2 * 64);
    packW_kernel<<<12, 256>>>(tb2_w, tb2_b, Wp + 1 * WPSTRIDE, bp + 1 * 64, 3 * 16 * 64);
    packW_kernel<<<48, 256>>>(tb3_w, tb3_b, Wp + 2 * WPSTRIDE, bp + 2 * 64, 3 * 64 * 64);
    packW_kernel<<<12, 256>>>(tb4_w, tb4_b, Wp + 3 * WPSTRIDE, bp + 3 * 64, 3 * 16 * 64);
    packW_kernel<<<48, 256>>>(tb5_w, tb5_b, Wp + 4 * WPSTRIDE, bp + 4 * 64, 3 * 64 * 64);
    splitA_kernel<<<NNODE * NNODE / 256, 256>>>(A_hat, Ahi, Alo);

    const dim3 tbBlock(64, 2);
    const int tbGrid = R_TOTAL / 2;

    // block 1
    timeblock_kernel<2, 24, true><<<tbGrid, tbBlock>>>(x, Wp + 0 * WPSTRIDE, bp + 0 * 64, theta1, bufC);
    tsplitU_kernel<352><<<dim3(64, 11, BATCH), 256>>>(bufC, Uhi, Ulo);
    gemm_mma_kernel<352><<<dim3(16, 11, BATCH), 256, SMEM_G>>>(Ahi, Alo, Uhi, Ulo, bufD);
    timeblock_kernel<16, 22, false><<<tbGrid, tbBlock>>>(bufD, Wp + 1 * WPSTRIDE, bp + 1 * 64, nullptr, bufA);

    // block 2
    timeblock_kernel<64, 20, true><<<tbGrid, tbBlock>>>(bufA, Wp + 2 * WPSTRIDE, bp + 2 * 64, theta2, bufC);
    tsplitU_kernel<288><<<dim3(64, 9, BATCH), 256>>>(bufC, Uhi, Ulo);
    gemm_mma_kernel<288><<<dim3(16, 9, BATCH), 256, SMEM_G>>>(Ahi, Alo, Uhi, Ulo, bufD);
    timeblock_kernel<16, 18, false><<<tbGrid, tbBlock>>>(bufD, Wp + 3 * WPSTRIDE, bp + 3 * 64, nullptr, bufA);

    // head
    timeblock_kernel<64, 16, false><<<tbGrid, tbBlock>>>(bufA, Wp + 4 * WPSTRIDE, bp + 4 * 64, nullptr, bufB);
    fc_kernel<<<R_TOTAL / 8, dim3(32, 8)>>>(bufB, fully_w, fully_b, out);

    const int n4 = (NNODE * NNODE) / 4;
    copy4_kernel<<<(n4 + 255) / 256, 256>>>((const float4*)A_hat,
                                            (float4*)(out + (long)R_TOTAL * 12), n4);
}

// round 5
// speedup vs baseline: 2.2330x; 1.1029x over previous
#include <cuda_runtime.h>
#include <cuda_bf16.h>
#include <cstdint>
#include <math.h>

#define BATCH 16
#define NNODE 2048
#define R_TOTAL (BATCH * NNODE)

// ---------------- scratch (device globals) ----------------
__device__ __align__(16) float g_bufA[R_TOTAL * 18 * 64];              // tb3 fp32 out
__device__ __align__(16) float g_bufB[R_TOTAL * 14 * 64];              // tb5 fp32 out
__device__ __align__(16) float g_bufC[R_TOTAL * 22 * 16];              // u1 fp32
__device__ __align__(16) __nv_bfloat16 g_Ahi[NNODE * NNODE];
__device__ __align__(16) __nv_bfloat16 g_Alo[NNODE * NNODE];
__device__ __align__(16) __nv_bfloat16 g_Uhi[(size_t)BATCH * 352 * NNODE];
__device__ __align__(16) __nv_bfloat16 g_Ulo[(size_t)BATCH * 352 * NNODE];
__device__ __align__(16) __nv_bfloat16 g_Chi[(size_t)BATCH * 2048 * 352];
__device__ __align__(16) __nv_bfloat16 g_Clo[(size_t)BATCH * 2048 * 352];
__device__ __align__(16) __nv_bfloat16 g_Xh[(size_t)R_TOTAL * 20 * 64];
__device__ __align__(16) __nv_bfloat16 g_Xl[(size_t)R_TOTAL * 20 * 64];
__device__ __align__(16) __nv_bfloat16 g_Wth[4 * 128 * 192];
__device__ __align__(16) __nv_bfloat16 g_Wtl[4 * 128 * 192];
__device__ __align__(16) float2 g_Wp[3 * 64 * 64];
__device__ __align__(16) float2 g_bp[5][64];

// ---------------- f32x2 helpers ----------------
__device__ __forceinline__ unsigned long long pk2(float lo, float hi) {
    unsigned long long r;
    asm("mov.b64 %0, {%1, %2};" : "=l"(r) : "f"(lo), "f"(hi));
    return r;
}
__device__ __forceinline__ void fma2(unsigned long long& d, unsigned long long a,
                                     unsigned long long b) {
    asm("fma.rn.f32x2 %0, %1, %2, %0;" : "+l"(d) : "l"(a), "l"(b));
}
__device__ __forceinline__ float2 upk(unsigned long long v) {
    float lo, hi;
    asm("mov.b64 {%0, %1}, %2;" : "=f"(lo), "=f"(hi) : "l"(v));
    return make_float2(lo, hi);
}

// ---------------- mma / cp.async helpers ----------------
__device__ __forceinline__ uint32_t smem_u32(const void* p) {
    uint32_t a;
    asm("{ .reg .u64 t; cvta.to.shared.u64 t, %1; cvt.u32.u64 %0, t; }" : "=r"(a) : "l"(p));
    return a;
}
#define CP16(sa, gp) asm volatile("cp.async.ca.shared.global [%0], [%1], 16;" \
    :: "r"(sa), "l"(gp) : "memory")
#define CPCOMMIT() asm volatile("cp.async.commit_group;" ::: "memory")
#define CPWAIT1()  asm volatile("cp.async.wait_group 1;" ::: "memory")
#define CPWAIT0()  asm volatile("cp.async.wait_group 0;" ::: "memory")
#define LDSM4(r, a) asm volatile( \
    "ldmatrix.sync.aligned.m8n8.x4.shared.b16 {%0,%1,%2,%3}, [%4];" \
    : "=r"((r)[0]), "=r"((r)[1]), "=r"((r)[2]), "=r"((r)[3]) : "r"(a))
__device__ __forceinline__ void mma_bf16(float* c, const uint32_t* a,
                                         uint32_t b0, uint32_t b1) {
    asm volatile(
        "mma.sync.aligned.m16n8k16.row.col.f32.bf16.bf16.f32 "
        "{%0,%1,%2,%3}, {%4,%5,%6,%7}, {%8,%9}, {%0,%1,%2,%3};"
        : "+f"(c[0]), "+f"(c[1]), "+f"(c[2]), "+f"(c[3])
        : "r"(a[0]), "r"(a[1]), "r"(a[2]), "r"(a[3]), "r"(b0), "r"(b1));
}
__device__ __forceinline__ void split2(__nv_bfloat16* H, __nv_bfloat16* L,
                                       float a, float b) {
    __nv_bfloat162 h, l;
    h.x = __float2bfloat16(a); h.y = __float2bfloat16(b);
    l.x = __float2bfloat16(a - __bfloat162float(h.x));
    l.y = __float2bfloat16(b - __bfloat162float(h.y));
    *(__nv_bfloat162*)H = h;
    *(__nv_bfloat162*)L = l;
}

// ---------------- prep kernels ----------------
__global__ __launch_bounds__(256) void packW_kernel(const float* __restrict__ W,
    const float* __restrict__ B3, float2* __restrict__ Wp, float2* __restrict__ bp, int n)
{
    int i = blockIdx.x * 256 + threadIdx.x;
    if (i < n) Wp[i] = make_float2(W[i] + W[n + i], W[2 * n + i]);
    if (i < 64) bp[i] = make_float2(B3[i] + B3[64 + i], B3[128 + i]);
}

// Wt[n][KM], n = 2c+g interleaved (temp/gate), zero-padded k >= 3*CIN
__global__ __launch_bounds__(256) void packWt_kernel(const float* __restrict__ W,
    const float* __restrict__ B3, __nv_bfloat16* __restrict__ Wth,
    __nv_bfloat16* __restrict__ Wtl, float2* __restrict__ bp, int CIN, int KM)
{
    const int K = 3 * CIN;
    int i = blockIdx.x * 256 + threadIdx.x;
    if (i < 128 * KM) {
        int n = i / KM, k = i % KM;
        float v = 0.0f;
        if (k < K) {
            int c = n >> 1, g = n & 1;
            int kk = k / CIN, cin = k % CIN;
            if (g == 0) v = W[(kk * CIN + cin) * 64 + c] + W[((3 + kk) * CIN + cin) * 64 + c];
            else        v = W[((6 + kk) * CIN + cin) * 64 + c];
        }
        __nv_bfloat16 h = __float2bfloat16(v);
        Wth[i] = h;
        Wtl[i] = __float2bfloat16(v - __bfloat162float(h));
    }
    if (i < 64) bp[i] = make_float2(B3[i] + B3[64 + i], B3[128 + i]);
}

__global__ __launch_bounds__(256) void splitA_kernel(const float* __restrict__ A,
    __nv_bfloat16* __restrict__ hi, __nv_bfloat16* __restrict__ lo)
{
    int i = blockIdx.x * 256 + threadIdx.x;
    float a = A[i];
    __nv_bfloat16 h = __float2bfloat16(a);
    hi[i] = h;
    lo[i] = __float2bfloat16(a - __bfloat162float(h));
}

// U [z][2048][F] -> Ut hi/lo [z][F][2048] bf16 split
template <int F>
__global__ __launch_bounds__(256) void tsplitU_kernel(const float* __restrict__ U,
    __nv_bfloat16* __restrict__ th, __nv_bfloat16* __restrict__ tl)
{
    __shared__ float t[32][33];
    const int j0 = blockIdx.x * 32, f0 = blockIdx.y * 32, z = blockIdx.z;
    const int tx = threadIdx.x & 31, ty = threadIdx.x >> 5;
#pragma unroll
    for (int q = 0; q < 32; q += 8)
        t[ty + q][tx] = U[((size_t)z * 2048 + j0 + ty + q) * F + f0 + tx];
    __syncthreads();
#pragma unroll
    for (int q = 0; q < 32; q += 8) {
        float v = t[tx][ty + q];
        __nv_bfloat16 h = __float2bfloat16(v);
        size_t o = ((size_t)z * F + f0 + ty + q) * 2048 + j0 + tx;
        th[o] = h;
        tl[o] = __float2bfloat16(v - __bfloat162float(h));
    }
}

// fused: u = Y @ theta2 (64->16), transpose, bf16 split.  Y [R,18,64] -> U [z][288][2048]
__global__ __launch_bounds__(256) void theta_tsplit_kernel(
    const float* __restrict__ Y, const float* __restrict__ theta,
    __nv_bfloat16* __restrict__ Uh, __nv_bfloat16* __restrict__ Ul)
{
    __shared__ float ys[8 * 1156 + 4];   // 8 rows of 1152, pad 4 floats/row
    __shared__ float th[64 * 16];
    const int tid = threadIdx.x;
    const int j0 = blockIdx.x * 8, z = blockIdx.y;
    const long rbase = (long)z * 2048 + j0;
    const float4* src = (const float4*)(Y + rbase * 1152);
    for (int i = tid; i < 8 * 288; i += 256) {
        int j = i / 288, q = i % 288;
        ((float4*)ys)[j * 289 + q] = src[i];
    }
    for (int i = tid; i < 1024; i += 256) th[i] = theta[i];
    __syncthreads();
    for (int o = tid; o < 288 * 8; o += 256) {
        int j = o & 7, f = o >> 3;
        int t = f >> 4, p = f & 15;
        const float* yr = &ys[j * 1156 + t * 64];
        float s = 0.0f;
#pragma unroll
        for (int m = 0; m < 64; ++m) s = fmaf(yr[m], th[m * 16 + p], s);
        __nv_bfloat16 h = __float2bfloat16(s);
        size_t oo = ((size_t)z * 288 + f) * 2048 + j0 + j;
        Uh[oo] = h;
        Ul[oo] = __float2bfloat16(s - __bfloat162float(h));
    }
}

// ---------------- scalar timeblock (tb1 only, CIN=2) ----------------
template <int CIN, int TIN, bool FUSE>
__global__ __launch_bounds__(128) void timeblock_kernel(
    const float* __restrict__ X, const float2* __restrict__ Wp,
    const float2* __restrict__ bp, const float* __restrict__ theta,
    float* __restrict__ Y)
{
    constexpr int TOUT = TIN - 2;
    constexpr int ROWS = 2;
    __shared__ __align__(16) float Xs[ROWS * TIN * CIN];
    __shared__ __align__(16) float Ys[FUSE ? (ROWS * TOUT * 64) : 1];
    __shared__ __align__(16) float Ths[FUSE ? (64 * 16) : 1];

    const int co = threadIdx.x, r = threadIdx.y;
    const int tid = r * 64 + co;
    const long row0 = (long)blockIdx.x * ROWS;
    {
        const float4* src = (const float4*)(X + row0 * (TIN * CIN));
        float4* dst = (float4*)Xs;
        for (int i = tid; i < ROWS * TIN * CIN / 4; i += 128) dst[i] = src[i];
    }
    if (FUSE)
        for (int i = tid; i < 64 * 16; i += 128) Ths[i] = theta[i];
    __syncthreads();

    const float2 bb = bp[co];
    unsigned long long acc2[TOUT];
#pragma unroll
    for (int t = 0; t < TOUT; ++t) acc2[t] = pk2(bb.x, bb.y);

    const float* Xr = &Xs[r * TIN * CIN];
    for (int cin = 0; cin < CIN; ++cin) {
        unsigned long long xp[TIN];
#pragma unroll
        for (int t = 0; t < TIN; ++t) {
            const float v = Xr[t * CIN + cin];
            xp[t] = pk2(v, v);
        }
#pragma unroll
        for (int k = 0; k < 3; ++k) {
            const float2 wv = Wp[(k * CIN + cin) * 64 + co];
            const unsigned long long wp = pk2(wv.x, wv.y);
#pragma unroll
            for (int t = 0; t < TOUT; ++t) fma2(acc2[t], xp[t + k], wp);
        }
    }
#pragma unroll
    for (int t = 0; t < TOUT; ++t) {
        const float2 a = upk(acc2[t]);
        const float g = 1.0f / (1.0f + __expf(-a.y));
        float y = a.x * g;
        y = (y > 0.0f) ? y : 0.0f;
        if (FUSE) Ys[(r * TOUT + t) * 64 + co] = y;
        else Y[(row0 + r) * (long)(TOUT * 64) + t * 64 + co] = y;
    }
    if (FUSE) {
        __syncthreads();
        for (int o = tid; o < ROWS * TOUT * 16; o += 128) {
            const int p = o & 15, t = (o >> 4) % TOUT, rr = o / (16 * TOUT);
            float s = 0.0f;
#pragma unroll
            for (int m = 0; m < 64; ++m)
                s = fmaf(Ys[(rr * TOUT + t) * 64 + m], Ths[m * 16 + p], s);
            Y[(row0 + rr) * (long)(TOUT * 16) + t * 16 + p] = s;
        }
    }
}

// ---------------- conv-as-mma gated timeblock -------------------------------
// X hi/lo bf16 [R, TIN*CIN]; Wt hi/lo [128][KM] (n=2c+g interleaved);
// out: relu(temp*sigmoid(gate)) as fp32 [R,TOUT,64] or bf16 hi/lo split.
template <int CIN, int TIN, int G, bool OUT32>
__global__ __launch_bounds__(256) void convmma_kernel(
    const __nv_bfloat16* __restrict__ Xh_g, const __nv_bfloat16* __restrict__ Xl_g,
    const __nv_bfloat16* __restrict__ Wh_g, const __nv_bfloat16* __restrict__ Wl_g,
    const float2* __restrict__ bp,
    float* __restrict__ Yf, __nv_bfloat16* __restrict__ Yh, __nv_bfloat16* __restrict__ Yl)
{
    constexpr int TOUT = TIN - 2;
    constexpr int K = 3 * CIN;
    constexpr int KM = (K + 31) / 32 * 32;
    constexpr int KP = KM + 8;
    constexpr int TS = CIN + 8;                 // padded t-stride (elements)
    constexpr int ROWEL = TIN * TS;
    constexpr int MROWS = G * TOUT;
    constexpr int XSZ = (G * ROWEL + 32) * 2;   // +32el tail (read by K-pad terms)

    constexpr uint32_t XH = 0;
    constexpr uint32_t XL = XH + XSZ;
    constexpr uint32_t WH = XL + XSZ;
    constexpr uint32_t WL = WH + 128 * KP * 2;
    constexpr uint32_t BIAS = WL + 128 * KP * 2;

    extern __shared__ __align__(128) char sm[];
    const uint32_t sb = smem_u32(sm);
    const int tid = threadIdx.x, w = tid >> 5, lane = tid & 31;
    const long r0 = (long)blockIdx.x * G;

    // stage X (t-padded rows)
    constexpr int XCH = G * TIN * CIN / 8;
    for (int i = tid; i < XCH; i += 256) {
        const int r = i / (TIN * CIN / 8);
        const int rem = i % (TIN * CIN / 8);
        const int t = rem / (CIN / 8);
        const int c8 = rem % (CIN / 8);
        long gr = r0 + r; if (gr >= R_TOTAL) gr = R_TOTAL - 1;
        const size_t gs = (size_t)gr * (TIN * CIN) + t * CIN + c8 * 8;
        const uint32_t d = (uint32_t)(r * ROWEL + t * TS + c8 * 8) * 2;
        CP16(sb + XH + d, Xh_g + gs);
        CP16(sb + XL + d, Xl_g + gs);
    }
    // stage W
    constexpr int WCH = 128 * KM / 8;
    for (int i = tid; i < WCH; i += 256) {
        const int n = i / (KM / 8), kc = i % (KM / 8);
        const size_t gs = (size_t)n * KM + kc * 8;
        const uint32_t d = (uint32_t)(n * KP + kc * 8) * 2;
        CP16(sb + WH + d, Wh_g + gs);
        CP16(sb + WL + d, Wl_g + gs);
    }
    CPCOMMIT();
    if (tid < 64) *(float2*)(sm + BIAS + tid * 8) = bp[tid];
    if (tid < 32) {   // zero the X tails (avoid NaN*0 in padded K terms)
        ((__nv_bfloat16*)(sm + XH))[G * ROWEL + tid] = __float2bfloat16(0.0f);
        ((__nv_bfloat16*)(sm + XL))[G * ROWEL + tid] = __float2bfloat16(0.0f);
    }
    CPWAIT0();
    __syncthreads();

    // A per-lane sliding-window row base
    const int mA = w * 16 + (lane & 15);
    int rrA = mA / TOUT, ttA = mA % TOUT;
    if (mA >= MROWS) { rrA = 0; ttA = 0; }
    const uint32_t abase = (uint32_t)(rrA * ROWEL + ttA * TS) * 2;
    const int hi8 = (lane >> 4) * 8;
    const uint32_t bbase = (uint32_t)((lane & 7) * KP * 2 + (lane >> 3) * 16);

    float acc[16][4];
#pragma unroll
    for (int nt = 0; nt < 16; ++nt)
#pragma unroll
        for (int q = 0; q < 4; ++q) acc[nt][q] = 0.0f;

#pragma unroll
    for (int kc = 0; kc < KM / 32; ++kc) {
        uint32_t ah[2][4], al[2][4];
#pragma unroll
        for (int s = 0; s < 2; ++s) {
            const int e0 = (2 * kc + s) * 16 + hi8;
            const uint32_t off = (uint32_t)((e0 / CIN) * TS + (e0 % CIN)) * 2;
            LDSM4(ah[s], sb + XH + abase + off);
            LDSM4(al[s], sb + XL + abase + off);
        }
#pragma unroll
        for (int nt = 0; nt < 16; ++nt) {
            uint32_t bh[4], bl[4];
            const uint32_t bo = bbase + (uint32_t)(nt * 8 * KP * 2 + kc * 64);
            LDSM4(bh, sb + WH + bo);
            LDSM4(bl, sb + WL + bo);
            mma_bf16(acc[nt], ah[0], bh[0], bh[1]);
            mma_bf16(acc[nt], al[0], bh[0], bh[1]);
            mma_bf16(acc[nt], ah[0], bl[0], bl[1]);
            mma_bf16(acc[nt], ah[1], bh[2], bh[3]);
            mma_bf16(acc[nt], al[1], bh[2], bh[3]);
            mma_bf16(acc[nt], ah[1], bl[2], bl[3]);
        }
    }

    // epilogue: gate, relu, store
    const int rE = w * 16 + (lane >> 2);
#pragma unroll
    for (int half = 0; half < 2; ++half) {
        const int m = rE + half * 8;
        const int rr = m / TOUT, tt = m % TOUT;
        const long gr = r0 + rr;
        if (m < MROWS && gr < R_TOTAL) {
#pragma unroll
            for (int nt = 0; nt < 16; ++nt) {
                const int c = nt * 4 + (lane & 3);
                const float2 bb = *(const float2*)(sm + BIAS + c * 8);
                const float temp = acc[nt][half * 2 + 0] + bb.x;
                const float gate = acc[nt][half * 2 + 1] + bb.y;
                const float gv = 1.0f / (1.0f + __expf(-gate));
                float y = temp * gv;
                y = (y > 0.0f) ? y : 0.0f;
                const size_t o = ((size_t)gr * TOUT + tt) * 64 + c;
                if (OUT32) {
                    Yf[o] = y;
                } else {
                    __nv_bfloat16 h = __float2bfloat16(y);
                    Yh[o] = h;
                    Yl[o] = __float2bfloat16(y - __bfloat162float(h));
                }
            }
        }
    }
}

// ---------------- einsum GEMM: Chi/Clo = split(relu(A @ U[z])) --------------
template <int F>
__global__ __launch_bounds__(256) void gemm_mma_kernel(
    const __nv_bfloat16* __restrict__ Ahi, const __nv_bfloat16* __restrict__ Alo,
    const __nv_bfloat16* __restrict__ Uhi, const __nv_bfloat16* __restrict__ Ulo,
    __nv_bfloat16* __restrict__ Chi, __nv_bfloat16* __restrict__ Clo)
{
    constexpr uint32_t ALOFF = 128 * 80;
    constexpr uint32_t BHOFF = 2 * 128 * 80;
    constexpr uint32_t BLOFF = BHOFF + 32 * 80;
    constexpr uint32_t STG   = BLOFF + 32 * 80;   // 25600 B/stage
    extern __shared__ __align__(128) char smc[];
    const uint32_t sb = smem_u32(smc);

    const int tid = threadIdx.x, w = tid >> 5, lane = tid & 31;
    const int m0 = blockIdx.x * 128, n0 = blockIdx.y * 32, z = blockIdx.z;

    const __nv_bfloat16* Ah = Ahi + (size_t)m0 * 2048;
    const __nv_bfloat16* Al = Alo + (size_t)m0 * 2048;
    const __nv_bfloat16* Bh = Uhi + ((size_t)z * F + n0) * 2048;
    const __nv_bfloat16* Bl = Ulo + ((size_t)z * F + n0) * 2048;

    const int ra = tid >> 2;
    const uint32_t cb = (tid & 3) * 16;
    const int ce = (tid & 3) * 8;
    const int rb = (tid & 127) >> 2;
    const uint32_t cbB = ((tid & 127) & 3) * 16;
    const int ceB = ((tid & 127) & 3) * 8;
    const __nv_bfloat16* Bt = (tid < 128) ? Bh : Bl;
    const uint32_t boff = (tid < 128) ? BHOFF : BLOFF;

#define LOAD_STAGE(buf, k0) do {                                               \
    const uint32_t st_ = sb + (buf) * STG;                                     \
    CP16(st_ + ra * 80 + cb,                Ah + (size_t)ra * 2048 + (k0) + ce);\
    CP16(st_ + (ra + 64) * 80 + cb,         Ah + (size_t)(ra + 64) * 2048 + (k0) + ce);\
    CP16(st_ + ALOFF + ra * 80 + cb,        Al + (size_t)ra * 2048 + (k0) + ce);\
    CP16(st_ + ALOFF + (ra + 64) * 80 + cb, Al + (size_t)(ra + 64) * 2048 + (k0) + ce);\
    CP16(st_ + boff + rb * 80 + cbB,        Bt + (size_t)rb * 2048 + (k0) + ceB);\
    CPCOMMIT();                                                                \
} while (0)

    float acc[4][4];
#pragma unroll
    for (int i = 0; i < 4; ++i)
#pragma unroll
        for (int j = 0; j < 4; ++j) acc[i][j] = 0.0f;

    LOAD_STAGE(0, 0);
    const uint32_t aoff = (uint32_t)((w * 16 + (lane & 15)) * 80 + (lane >> 4) * 16);
    const uint32_t boff2 = (uint32_t)((lane & 7) * 80 + (lane >> 3) * 16);

    for (int it = 0; it < 64; ++it) {
        if (it < 63) { LOAD_STAGE((it + 1) & 1, (it + 1) * 32); CPWAIT1(); }
        else CPWAIT0();
        __syncthreads();
        const uint32_t st = sb + (it & 1) * STG;
        uint32_t aF[2][2][4], bF[2][4][4];
        LDSM4(aF[0][0], st + aoff);
        LDSM4(aF[0][1], st + aoff + 32);
        LDSM4(aF[1][0], st + ALOFF + aoff);
        LDSM4(aF[1][1], st + ALOFF + aoff + 32);
#pragma unroll
        for (int nt = 0; nt < 4; ++nt) {
            LDSM4(bF[0][nt], st + BHOFF + boff2 + nt * 8 * 80);
            LDSM4(bF[1][nt], st + BLOFF + boff2 + nt * 8 * 80);
        }
#pragma unroll
        for (int ks = 0; ks < 2; ++ks)
#pragma unroll
            for (int nt = 0; nt < 4; ++nt) {
                mma_bf16(acc[nt], aF[0][ks], bF[0][nt][2 * ks], bF[0][nt][2 * ks + 1]);
                mma_bf16(acc[nt], aF[0][ks], bF[1][nt][2 * ks], bF[1][nt][2 * ks + 1]);
                mma_bf16(acc[nt], aF[1][ks], bF[0][nt][2 * ks], bF[0][nt][2 * ks + 1]);
            }
        __syncthreads();
    }

    const int mr = m0 + w * 16 + (lane >> 2);
    const int cc = n0 + 2 * (lane & 3);
    __nv_bfloat16* H0 = Chi + ((size_t)z * 2048 + mr) * F + cc;
    __nv_bfloat16* L0 = Clo + ((size_t)z * 2048 + mr) * F + cc;
    __nv_bfloat16* H1 = H0 + 8 * (size_t)F;
    __nv_bfloat16* L1 = L0 + 8 * (size_t)F;
#pragma unroll
    for (int nt = 0; nt < 4; ++nt) {
        split2(H0 + nt * 8, L0 + nt * 8, fmaxf(acc[nt][0], 0.0f), fmaxf(acc[nt][1], 0.0f));
        split2(H1 + nt * 8, L1 + nt * 8, fmaxf(acc[nt][2], 0.0f), fmaxf(acc[nt][3], 0.0f));
    }
#undef LOAD_STAGE
}

// ---------------- FC + copy ----------------
__global__ __launch_bounds__(256) void fc_kernel(const float* __restrict__ X,
    const float* __restrict__ W, const float* __restrict__ bias, float* __restrict__ out)
{
    const int lane = threadIdx.x;
    const long row = (long)blockIdx.x * blockDim.y + threadIdx.y;
    const float* x = X + row * 896;
    float acc[12];
#pragma unroll
    for (int p = 0; p < 12; ++p) acc[p] = 0.0f;
    for (int e = lane; e < 896; e += 32) {
        const float xv = x[e];
#pragma unroll
        for (int p = 0; p < 12; ++p) acc[p] = fmaf(xv, W[e * 12 + p], acc[p]);
    }
#pragma unroll
    for (int off = 16; off > 0; off >>= 1)
#pragma unroll
        for (int p = 0; p < 12; ++p) acc[p] += __shfl_down_sync(0xffffffffu, acc[p], off);
    if (lane == 0)
#pragma unroll
        for (int p = 0; p < 12; ++p) out[row * 12 + p] = acc[p] + bias[p];
}

__global__ __launch_bounds__(256) void copy4_kernel(const float4* __restrict__ s,
                                                    float4* __restrict__ d, int n4)
{
    const int i = blockIdx.x * blockDim.x + threadIdx.x;
    if (i < n4) d[i] = s[i];
}

// ---------------- launch ----------------
extern "C" void kernel_launch(void* const* d_in, const int* in_sizes, int n_in,
                              void* d_out, int out_size)
{
    const float* x       = (const float*)d_in[0];
    const float* A_hat   = (const float*)d_in[1];
    const float* tb1_w   = (const float*)d_in[2];
    const float* tb1_b   = (const float*)d_in[3];
    const float* theta1  = (const float*)d_in[4];
    const float* tb2_w   = (const float*)d_in[5];
    const float* tb2_b   = (const float*)d_in[6];
    const float* tb3_w   = (const float*)d_in[7];
    const float* tb3_b   = (const float*)d_in[8];
    const float* theta2  = (const float*)d_in[9];
    const float* tb4_w   = (const float*)d_in[10];
    const float* tb4_b   = (const float*)d_in[11];
    const float* tb5_w   = (const float*)d_in[12];
    const float* tb5_b   = (const float*)d_in[13];
    const float* fully_w = (const float*)d_in[14];
    const float* fully_b = (const float*)d_in[15];
    float* out = (float*)d_out;

    float *bufA, *bufB, *bufC;
    __nv_bfloat16 *Ahi, *Alo, *Uhi, *Ulo, *Chi, *Clo, *Xh, *Xl, *Wth, *Wtl;
    float2 *Wp, *bp;
    cudaGetSymbolAddress((void**)&bufA, g_bufA);
    cudaGetSymbolAddress((void**)&bufB, g_bufB);
    cudaGetSymbolAddress((void**)&bufC, g_bufC);
    cudaGetSymbolAddress((void**)&Ahi, g_Ahi);
    cudaGetSymbolAddress((void**)&Alo, g_Alo);
    cudaGetSymbolAddress((void**)&Uhi, g_Uhi);
    cudaGetSymbolAddress((void**)&Ulo, g_Ulo);
    cudaGetSymbolAddress((void**)&Chi, g_Chi);
    cudaGetSymbolAddress((void**)&Clo, g_Clo);
    cudaGetSymbolAddress((void**)&Xh, g_Xh);
    cudaGetSymbolAddress((void**)&Xl, g_Xl);
    cudaGetSymbolAddress((void**)&Wth, g_Wth);
    cudaGetSymbolAddress((void**)&Wtl, g_Wtl);
    cudaGetSymbolAddress((void**)&Wp, g_Wp);
    cudaGetSymbolAddress((void**)&bp, g_bp);

    constexpr int WS = 128 * 192;
    constexpr int SMEM_G = 2 * 25600;
    constexpr int SM_TB2 = 50176, SM_TB3 = 143360, SM_TB4 = 51328, SM_TB5 = 144512;
    cudaFuncSetAttribute(gemm_mma_kernel<352>, cudaFuncAttributeMaxDynamicSharedMemorySize, SMEM_G);
    cudaFuncSetAttribute(gemm_mma_kernel<288>, cudaFuncAttributeMaxDynamicSharedMemorySize, SMEM_G);
    cudaFuncSetAttribute(convmma_kernel<16, 22, 6, false>, cudaFuncAttributeMaxDynamicSharedMemorySize, SM_TB2);
    cudaFuncSetAttribute(convmma_kernel<64, 20, 7, true>,  cudaFuncAttributeMaxDynamicSharedMemorySize, SM_TB3);
    cudaFuncSetAttribute(convmma_kernel<16, 18, 8, false>, cudaFuncAttributeMaxDynamicSharedMemorySize, SM_TB4);
    cudaFuncSetAttribute(convmma_kernel<64, 16, 9, true>,  cudaFuncAttributeMaxDynamicSharedMemorySize, SM_TB5);

    // prep
    packW_kernel<<<2, 256>>>(tb1_w, tb1_b, Wp, (float2*)bp + 0 * 64, 3 * 2 * 64);
    packWt_kernel<<<32, 256>>>(tb2_w, tb2_b, Wth + 0 * WS, Wtl + 0 * WS, (float2*)bp + 1 * 64, 16, 64);
    packWt_kernel<<<96, 256>>>(tb3_w, tb3_b, Wth + 1 * WS, Wtl + 1 * WS, (float2*)bp + 2 * 64, 64, 192);
    packWt_kernel<<<32, 256>>>(tb4_w, tb4_b, Wth + 2 * WS, Wtl + 2 * WS, (float2*)bp + 3 * 64, 16, 64);
    packWt_kernel<<<96, 256>>>(tb5_w, tb5_b, Wth + 3 * WS, Wtl + 3 * WS, (float2*)bp + 4 * 64, 64, 192);
    splitA_kernel<<<NNODE * NNODE / 256, 256>>>(A_hat, Ahi, Alo);

    // block 1
    timeblock_kernel<2, 24, true><<<R_TOTAL / 2, dim3(64, 2)>>>(x, Wp, (float2*)bp + 0 * 64, theta1, bufC);
    tsplitU_kernel<352><<<dim3(64, 11, BATCH), 256>>>(bufC, Uhi, Ulo);
    gemm_mma_kernel<352><<<dim3(16, 11, BATCH), 256, SMEM_G>>>(Ahi, Alo, Uhi, Ulo, Chi, Clo);
    convmma_kernel<16, 22, 6, false><<<(R_TOTAL + 5) / 6, 256, SM_TB2>>>(
        Chi, Clo, Wth + 0 * WS, Wtl + 0 * WS, (float2*)bp + 1 * 64, nullptr, Xh, Xl);

    // block 2
    convmma_kernel<64, 20, 7, true><<<(R_TOTAL + 6) / 7, 256, SM_TB3>>>(
        Xh, Xl, Wth + 1 * WS, Wtl + 1 * WS, (float2*)bp + 2 * 64, bufA, nullptr, nullptr);
    theta_tsplit_kernel<<<dim3(256, 16), 256>>>(bufA, theta2, Uhi, Ulo);
    gemm_mma_kernel<288><<<dim3(16, 9, BATCH), 256, SMEM_G>>>(Ahi, Alo, Uhi, Ulo, Chi, Clo);
    convmma_kernel<16, 18, 8, false><<<R_TOTAL / 8, 256, SM_TB4>>>(
        Chi, Clo, Wth + 2 * WS, Wtl + 2 * WS, (float2*)bp + 3 * 64, nullptr, Xh, Xl);

    // head
    convmma_kernel<64, 16, 9, true><<<(R_TOTAL + 8) / 9, 256, SM_TB5>>>(
        Xh, Xl, Wth + 3 * WS, Wtl + 3 * WS, (float2*)bp + 4 * 64, bufB, nullptr, nullptr);
    fc_kernel<<<R_TOTAL / 8, dim3(32, 8)>>>(bufB, fully_w, fully_b, out);

    const int n4 = (NNODE * NNODE) / 4;
    copy4_kernel<<<(n4 + 255) / 256, 256>>>((const float4*)A_hat,
                                            (float4*)(out + (long)R_TOTAL * 12), n4);
}

// round 6
// speedup vs baseline: 2.9548x; 1.3233x over previous
#include <cuda_runtime.h>
#include <cuda_fp16.h>
#include <cstdint>
#include <math.h>

#define BATCH 16
#define NNODE 2048
#define R_TOTAL (BATCH * NNODE)

// ---------------- scratch (device globals) ----------------
__device__ __align__(16) float  g_bufB[R_TOTAL * 14 * 64];          // tb5 fp32 out
__device__ __align__(16) float  g_bufC[R_TOTAL * 22 * 16];          // u1 fp32
__device__ __align__(16) __half g_Ah[NNODE * NNODE];
__device__ __align__(16) __half g_Uh[(size_t)BATCH * 352 * NNODE];
__device__ __align__(16) __half g_Ul[(size_t)BATCH * 352 * NNODE];
__device__ __align__(16) __half g_Ch[(size_t)BATCH * 2048 * 352];   // einsum out
__device__ __align__(16) __half g_Xh[(size_t)R_TOTAL * 20 * 64];    // tb2/tb4 out
__device__ __align__(16) __half g_Yh[(size_t)R_TOTAL * 18 * 64];    // tb3 out
__device__ __align__(16) __half g_Wth[4 * 128 * 192];
__device__ __align__(16) __half g_Wtl[4 * 128 * 192];
__device__ __align__(16) float2 g_Wp[3 * 64 * 64];
__device__ __align__(16) float2 g_bp[5][64];

// ---------------- f32x2 helpers (tb1 scalar path) ----------------
__device__ __forceinline__ unsigned long long pk2(float lo, float hi) {
    unsigned long long r;
    asm("mov.b64 %0, {%1, %2};" : "=l"(r) : "f"(lo), "f"(hi));
    return r;
}
__device__ __forceinline__ void fma2(unsigned long long& d, unsigned long long a,
                                     unsigned long long b) {
    asm("fma.rn.f32x2 %0, %1, %2, %0;" : "+l"(d) : "l"(a), "l"(b));
}
__device__ __forceinline__ float2 upk(unsigned long long v) {
    float lo, hi;
    asm("mov.b64 {%0, %1}, %2;" : "=f"(lo), "=f"(hi) : "l"(v));
    return make_float2(lo, hi);
}

// ---------------- mma / cp.async helpers ----------------
__device__ __forceinline__ uint32_t smem_u32(const void* p) {
    uint32_t a;
    asm("{ .reg .u64 t; cvta.to.shared.u64 t, %1; cvt.u32.u64 %0, t; }" : "=r"(a) : "l"(p));
    return a;
}
#define CP16(sa, gp) asm volatile("cp.async.ca.shared.global [%0], [%1], 16;" \
    :: "r"(sa), "l"(gp) : "memory")
#define CPCOMMIT() asm volatile("cp.async.commit_group;" ::: "memory")
#define CPWAIT1()  asm volatile("cp.async.wait_group 1;" ::: "memory")
#define CPWAIT0()  asm volatile("cp.async.wait_group 0;" ::: "memory")
#define LDSM4(r, a) asm volatile( \
    "ldmatrix.sync.aligned.m8n8.x4.shared.b16 {%0,%1,%2,%3}, [%4];" \
    : "=r"((r)[0]), "=r"((r)[1]), "=r"((r)[2]), "=r"((r)[3]) : "r"(a))
__device__ __forceinline__ void mma_f16(float* c, const uint32_t* a,
                                        uint32_t b0, uint32_t b1) {
    asm volatile(
        "mma.sync.aligned.m16n8k16.row.col.f32.f16.f16.f32 "
        "{%0,%1,%2,%3}, {%4,%5,%6,%7}, {%8,%9}, {%0,%1,%2,%3};"
        : "+f"(c[0]), "+f"(c[1]), "+f"(c[2]), "+f"(c[3])
        : "r"(a[0]), "r"(a[1]), "r"(a[2]), "r"(a[3]), "r"(b0), "r"(b1));
}

// ---------------- prep kernels ----------------
__global__ __launch_bounds__(256) void packW_kernel(const float* __restrict__ W,
    const float* __restrict__ B3, float2* __restrict__ Wp, float2* __restrict__ bp, int n)
{
    int i = blockIdx.x * 256 + threadIdx.x;
    if (i < n) Wp[i] = make_float2(W[i] + W[n + i], W[2 * n + i]);
    if (i < 64) bp[i] = make_float2(B3[i] + B3[64 + i], B3[128 + i]);
}

// Wt[n][KM] fp16 hi/lo, n = 2c+g interleaved, zero-padded k >= 3*CIN
__global__ __launch_bounds__(256) void packWt_kernel(const float* __restrict__ W,
    const float* __restrict__ B3, __half* __restrict__ Wth,
    __half* __restrict__ Wtl, float2* __restrict__ bp, int CIN, int KM)
{
    const int K = 3 * CIN;
    int i = blockIdx.x * 256 + threadIdx.x;
    if (i < 128 * KM) {
        int n = i / KM, k = i % KM;
        float v = 0.0f;
        if (k < K) {
            int c = n >> 1, g = n & 1;
            int kk = k / CIN, cin = k % CIN;
            if (g == 0) v = W[(kk * CIN + cin) * 64 + c] + W[((3 + kk) * CIN + cin) * 64 + c];
            else        v = W[((6 + kk) * CIN + cin) * 64 + c];
        }
        __half h = __float2half(v);
        Wth[i] = h;
        Wtl[i] = __float2half(v - __half2float(h));
    }
    if (i < 64) bp[i] = make_float2(B3[i] + B3[64 + i], B3[128 + i]);
}

__global__ __launch_bounds__(256) void halfA_kernel(const float* __restrict__ A,
                                                    __half* __restrict__ H)
{
    int i = blockIdx.x * 256 + threadIdx.x;
    H[i] = __float2half(A[i]);
}

// U [z][2048][F] fp32 -> Ut hi/lo fp16 [z][F][2048]
template <int F>
__global__ __launch_bounds__(256) void tsplitU_kernel(const float* __restrict__ U,
    __half* __restrict__ th, __half* __restrict__ tl)
{
    __shared__ float t[32][33];
    const int j0 = blockIdx.x * 32, f0 = blockIdx.y * 32, z = blockIdx.z;
    const int tx = threadIdx.x & 31, ty = threadIdx.x >> 5;
#pragma unroll
    for (int q = 0; q < 32; q += 8)
        t[ty + q][tx] = U[((size_t)z * 2048 + j0 + ty + q) * F + f0 + tx];
    __syncthreads();
#pragma unroll
    for (int q = 0; q < 32; q += 8) {
        float v = t[tx][ty + q];
        __half h = __float2half(v);
        size_t o = ((size_t)z * F + f0 + ty + q) * 2048 + j0 + tx;
        th[o] = h;
        tl[o] = __float2half(v - __half2float(h));
    }
}

// fused: u = Y @ theta2, transpose, fp16 split.  Y fp16 [R,18,64] -> U [z][288][2048]
__global__ __launch_bounds__(256) void theta_tsplit_kernel(
    const __half* __restrict__ Y, const float* __restrict__ theta,
    __half* __restrict__ Uh, __half* __restrict__ Ul)
{
    __shared__ float ys[8 * 1156 + 4];
    __shared__ float th[64 * 16];
    const int tid = threadIdx.x;
    const int j0 = blockIdx.x * 8, z = blockIdx.y;
    const long rbase = (long)z * 2048 + j0;
    const uint4* src = (const uint4*)(Y + rbase * 1152);   // 8 halves / uint4, 144/row
    for (int i = tid; i < 8 * 144; i += 256) {
        int j = i / 144, q = i % 144;
        uint4 v = src[i];
        const __half2* hp = (const __half2*)&v;
        float* d = &ys[j * 1156 + q * 8];
#pragma unroll
        for (int e = 0; e < 4; ++e) {
            float2 f = __half22float2(hp[e]);
            d[2 * e] = f.x; d[2 * e + 1] = f.y;
        }
    }
    for (int i = tid; i < 1024; i += 256) th[i] = theta[i];
    __syncthreads();
    for (int o = tid; o < 288 * 8; o += 256) {
        int j = o & 7, f = o >> 3;
        int t = f >> 4, p = f & 15;
        const float* yr = &ys[j * 1156 + t * 64];
        float s = 0.0f;
#pragma unroll
        for (int m = 0; m < 64; ++m) s = fmaf(yr[m], th[m * 16 + p], s);
        __half h = __float2half(s);
        size_t oo = ((size_t)z * 288 + f) * 2048 + j0 + j;
        Uh[oo] = h;
        Ul[oo] = __float2half(s - __half2float(h));
    }
}

// ---------------- scalar timeblock (tb1, CIN=2) ----------------
template <int CIN, int TIN>
__global__ __launch_bounds__(128) void timeblock_kernel(
    const float* __restrict__ X, const float2* __restrict__ Wp,
    const float2* __restrict__ bp, const float* __restrict__ theta,
    float* __restrict__ Y)
{
    constexpr int TOUT = TIN - 2;
    constexpr int ROWS = 2;
    __shared__ __align__(16) float Xs[ROWS * TIN * CIN];
    __shared__ __align__(16) float Ys[ROWS * TOUT * 64];
    __shared__ __align__(16) float Ths[64 * 16];

    const int co = threadIdx.x, r = threadIdx.y;
    const int tid = r * 64 + co;
    const long row0 = (long)blockIdx.x * ROWS;
    {
        const float4* src = (const float4*)(X + row0 * (TIN * CIN));
        float4* dst = (float4*)Xs;
        for (int i = tid; i < ROWS * TIN * CIN / 4; i += 128) dst[i] = src[i];
    }
    for (int i = tid; i < 64 * 16; i += 128) Ths[i] = theta[i];
    __syncthreads();

    const float2 bb = bp[co];
    unsigned long long acc2[TOUT];
#pragma unroll
    for (int t = 0; t < TOUT; ++t) acc2[t] = pk2(bb.x, bb.y);

    const float* Xr = &Xs[r * TIN * CIN];
    for (int cin = 0; cin < CIN; ++cin) {
        unsigned long long xp[TIN];
#pragma unroll
        for (int t = 0; t < TIN; ++t) {
            const float v = Xr[t * CIN + cin];
            xp[t] = pk2(v, v);
        }
#pragma unroll
        for (int k = 0; k < 3; ++k) {
            const float2 wv = Wp[(k * CIN + cin) * 64 + co];
            const unsigned long long wp = pk2(wv.x, wv.y);
#pragma unroll
            for (int t = 0; t < TOUT; ++t) fma2(acc2[t], xp[t + k], wp);
        }
    }
#pragma unroll
    for (int t = 0; t < TOUT; ++t) {
        const float2 a = upk(acc2[t]);
        const float g = 1.0f / (1.0f + __expf(-a.y));
        float y = a.x * g;
        y = (y > 0.0f) ? y : 0.0f;
        Ys[(r * TOUT + t) * 64 + co] = y;
    }
    __syncthreads();
    for (int o = tid; o < ROWS * TOUT * 16; o += 128) {
        const int p = o & 15, t = (o >> 4) % TOUT, rr = o / (16 * TOUT);
        float s = 0.0f;
#pragma unroll
        for (int m = 0; m < 64; ++m)
            s = fmaf(Ys[(rr * TOUT + t) * 64 + m], Ths[m * 16 + p], s);
        Y[(row0 + rr) * (long)(TOUT * 16) + t * 16 + p] = s;
    }
}

// ---------------- conv-as-mma gated timeblock (2-term fp16) -----------------
// X fp16 single [R, TIN*CIN]; W hi/lo [128][KM]; S slabs per CTA (W resident).
template <int CIN, int TIN, int G, int S, bool OUT32>
__global__ __launch_bounds__(256) void convmma_kernel(
    const __half* __restrict__ Xg,
    const __half* __restrict__ Whg, const __half* __restrict__ Wlg,
    const float2* __restrict__ bp,
    float* __restrict__ Yf, __half* __restrict__ Yh)
{
    constexpr int TOUT = TIN - 2;
    constexpr int K = 3 * CIN;
    constexpr int KM = (K + 31) / 32 * 32;
    constexpr int KP = KM + 8;
    constexpr int TS = CIN + 8;
    constexpr int ROWEL = TIN * TS;
    constexpr int MROWS = G * TOUT;
    constexpr int XSZ = (G * ROWEL + 32) * 2;

    constexpr uint32_t XB0 = 0;
    constexpr uint32_t XB1 = XSZ;
    constexpr uint32_t WH = 2 * XSZ;
    constexpr uint32_t WL = WH + 128 * KP * 2;
    constexpr uint32_t BIAS = WL + 128 * KP * 2;

    extern __shared__ __align__(128) char sm[];
    const uint32_t sb = smem_u32(sm);
    const int tid = threadIdx.x, w = tid >> 5, lane = tid & 31;
    const long base_r0 = (long)blockIdx.x * (G * S);

    // stage W (resident across slabs)
    constexpr int WCH = 128 * KM / 8;
    for (int i = tid; i < WCH; i += 256) {
        const int n = i / (KM / 8), kc = i % (KM / 8);
        const size_t gs = (size_t)n * KM + kc * 8;
        const uint32_t d = (uint32_t)(n * KP + kc * 8) * 2;
        CP16(sb + WH + d, Whg + gs);
        CP16(sb + WL + d, Wlg + gs);
    }

#define STAGE_X(bufoff, slab) do {                                             \
    const long r0_ = base_r0 + (long)(slab) * G;                               \
    for (int i = tid; i < G * TIN * CIN / 8; i += 256) {                       \
        const int r_ = i / (TIN * CIN / 8);                                    \
        const int rem_ = i % (TIN * CIN / 8);                                  \
        const int t_ = rem_ / (CIN / 8);                                       \
        const int c8_ = rem_ % (CIN / 8);                                      \
        long gr_ = r0_ + r_; if (gr_ >= R_TOTAL) gr_ = R_TOTAL - 1;            \
        CP16(sb + (bufoff) + (uint32_t)(r_ * ROWEL + t_ * TS + c8_ * 8) * 2,   \
             Xg + (size_t)gr_ * (TIN * CIN) + t_ * CIN + c8_ * 8);             \
    }                                                                          \
} while (0)

    STAGE_X(XB0, 0);
    CPCOMMIT();
    if (tid < 64) *(float2*)(sm + BIAS + tid * 8) = bp[tid];
    if (tid < 32) {   // zero X tails of both buffers
        ((__half*)(sm + XB0))[G * ROWEL + tid] = __float2half(0.0f);
        ((__half*)(sm + XB1))[G * ROWEL + tid] = __float2half(0.0f);
    }

    // per-lane A (sliding window) base
    const int mA = w * 16 + (lane & 15);
    int rrA = mA / TOUT, ttA = mA % TOUT;
    if (mA >= MROWS) { rrA = 0; ttA = 0; }
    const uint32_t abase = (uint32_t)(rrA * ROWEL + ttA * TS) * 2;
    const int hi8 = (lane >> 4) * 8;
    const uint32_t bbase = (uint32_t)((lane & 7) * KP * 2 + (lane >> 3) * 16);
    const int rE = w * 16 + (lane >> 2);

    for (int s = 0; s < S; ++s) {
        if (s + 1 < S) {
            STAGE_X((s + 1) & 1 ? XB1 : XB0, s + 1);
            CPCOMMIT();
            CPWAIT1();
        } else {
            CPWAIT0();
        }
        __syncthreads();

        const uint32_t xb = sb + ((s & 1) ? XB1 : XB0);
        float acc[16][4];
#pragma unroll
        for (int nt = 0; nt < 16; ++nt)
#pragma unroll
            for (int q = 0; q < 4; ++q) acc[nt][q] = 0.0f;

#pragma unroll
        for (int kc = 0; kc < KM / 32; ++kc) {
            uint32_t ah[2][4];
#pragma unroll
            for (int s2 = 0; s2 < 2; ++s2) {
                const int e0 = (2 * kc + s2) * 16 + hi8;
                const uint32_t off = (uint32_t)((e0 / CIN) * TS + (e0 % CIN)) * 2;
                LDSM4(ah[s2], xb + abase + off);
            }
#pragma unroll
            for (int nt = 0; nt < 16; ++nt) {
                uint32_t bh[4], bl[4];
                const uint32_t bo = bbase + (uint32_t)(nt * 8 * KP * 2 + kc * 64);
                LDSM4(bh, sb + WH + bo);
                LDSM4(bl, sb + WL + bo);
                mma_f16(acc[nt], ah[0], bh[0], bh[1]);
                mma_f16(acc[nt], ah[0], bl[0], bl[1]);
                mma_f16(acc[nt], ah[1], bh[2], bh[3]);
                mma_f16(acc[nt], ah[1], bl[2], bl[3]);
            }
        }

        // epilogue: gate, relu, store
        const long r0s = base_r0 + (long)s * G;
#pragma unroll
        for (int hf = 0; hf < 2; ++hf) {
            const int m = rE + hf * 8;
            const int rr = m / TOUT, tt = m % TOUT;
            const long gr = r0s + rr;
            if (m < MROWS && gr < R_TOTAL) {
#pragma unroll
                for (int nt = 0; nt < 16; ++nt) {
                    const int c = nt * 4 + (lane & 3);
                    const float2 bb = *(const float2*)(sm + BIAS + c * 8);
                    const float temp = acc[nt][hf * 2 + 0] + bb.x;
                    const float gate = acc[nt][hf * 2 + 1] + bb.y;
                    const float gv = 1.0f / (1.0f + __expf(-gate));
                    float y = temp * gv;
                    y = (y > 0.0f) ? y : 0.0f;
                    const size_t o = ((size_t)gr * TOUT + tt) * 64 + c;
                    if (OUT32) Yf[o] = y;
                    else       Yh[o] = __float2half(y);
                }
            }
        }
        __syncthreads();
    }
#undef STAGE_X
}

// ---------------- einsum GEMM: Ch = fp16(relu(A @ U[z])) --------------------
// A fp16 single [2048,2048]; Ut hi/lo fp16 [z][F][2048]; 2-term mma.
template <int F>
__global__ __launch_bounds__(256) void gemm_mma_kernel(
    const __half* __restrict__ Ah_g,
    const __half* __restrict__ Uh_g, const __half* __restrict__ Ul_g,
    __half* __restrict__ Ch_g)
{
    constexpr uint32_t BH = 128 * 80;        // 10240
    constexpr uint32_t BL = BH + 32 * 80;    // 12800
    constexpr uint32_t STG = BL + 32 * 80;   // 15360 B/stage
    extern __shared__ __align__(128) char smc[];
    const uint32_t sb = smem_u32(smc);

    const int tid = threadIdx.x, w = tid >> 5, lane = tid & 31;
    const int m0 = blockIdx.x * 128, n0 = blockIdx.y * 32, z = blockIdx.z;

    const __half* Ab = Ah_g + (size_t)m0 * 2048;
    const __half* Bh = Uh_g + ((size_t)z * F + n0) * 2048;
    const __half* Bl = Ul_g + ((size_t)z * F + n0) * 2048;

    const int ra = tid >> 1;                     // 0..127 A row
    const uint32_t acb = (tid & 1) * 32;         // byte col (half-row)
    const int ace = (tid & 1) * 16;              // elem col
    const int rbn = (tid & 127) >> 2;            // 0..31 B row
    const uint32_t cbB = ((tid & 127) & 3) * 16;
    const int ceB = ((tid & 127) & 3) * 8;
    const __half* Bt = (tid < 128) ? Bh : Bl;
    const uint32_t bo = (tid < 128) ? BH : BL;

#define LOAD_STAGE(buf, k0) do {                                               \
    const uint32_t st_ = sb + (buf) * STG;                                     \
    CP16(st_ + ra * 80 + acb,      Ab + (size_t)ra * 2048 + (k0) + ace);       \
    CP16(st_ + ra * 80 + acb + 16, Ab + (size_t)ra * 2048 + (k0) + ace + 8);   \
    CP16(st_ + bo + rbn * 80 + cbB, Bt + (size_t)rbn * 2048 + (k0) + ceB);     \
    CPCOMMIT();                                                                \
} while (0)

    float acc[4][4];
#pragma unroll
    for (int i = 0; i < 4; ++i)
#pragma unroll
        for (int j = 0; j < 4; ++j) acc[i][j] = 0.0f;

    LOAD_STAGE(0, 0);
    const uint32_t aoff = (uint32_t)((w * 16 + (lane & 15)) * 80 + (lane >> 4) * 16);
    const uint32_t boff2 = (uint32_t)((lane & 7) * 80 + (lane >> 3) * 16);

    for (int it = 0; it < 64; ++it) {
        if (it < 63) { LOAD_STAGE((it + 1) & 1, (it + 1) * 32); CPWAIT1(); }
        else CPWAIT0();
        __syncthreads();
        const uint32_t st = sb + (it & 1) * STG;
        uint32_t aF[2][4], bh[4][4], bl[4][4];
        LDSM4(aF[0], st + aoff);
        LDSM4(aF[1], st + aoff + 32);
#pragma unroll
        for (int nt = 0; nt < 4; ++nt) {
            LDSM4(bh[nt], st + BH + boff2 + nt * 8 * 80);
            LDSM4(bl[nt], st + BL + boff2 + nt * 8 * 80);
        }
#pragma unroll
        for (int ks = 0; ks < 2; ++ks)
#pragma unroll
            for (int nt = 0; nt < 4; ++nt) {
                mma_f16(acc[nt], aF[ks], bh[nt][2 * ks], bh[nt][2 * ks + 1]);
                mma_f16(acc[nt], aF[ks], bl[nt][2 * ks], bl[nt][2 * ks + 1]);
            }
        __syncthreads();
    }

    const int mr = m0 + w * 16 + (lane >> 2);
    const int cc = n0 + 2 * (lane & 3);
    __half* H0 = Ch_g + ((size_t)z * 2048 + mr) * F + cc;
    __half* H1 = H0 + 8 * (size_t)F;
#pragma unroll
    for (int nt = 0; nt < 4; ++nt) {
        *(__half2*)(H0 + nt * 8) = __floats2half2_rn(fmaxf(acc[nt][0], 0.0f),
                                                     fmaxf(acc[nt][1], 0.0f));
        *(__half2*)(H1 + nt * 8) = __floats2half2_rn(fmaxf(acc[nt][2], 0.0f),
                                                     fmaxf(acc[nt][3], 0.0f));
    }
#undef LOAD_STAGE
}

// ---------------- FC + copy ----------------
__global__ __launch_bounds__(256) void fc_kernel(const float* __restrict__ X,
    const float* __restrict__ W, const float* __restrict__ bias, float* __restrict__ out)
{
    const int lane = threadIdx.x;
    const long row = (long)blockIdx.x * blockDim.y + threadIdx.y;
    const float* x = X + row * 896;
    float acc[12];
#pragma unroll
    for (int p = 0; p < 12; ++p) acc[p] = 0.0f;
    for (int e = lane; e < 896; e += 32) {
        const float xv = x[e];
#pragma unroll
        for (int p = 0; p < 12; ++p) acc[p] = fmaf(xv, W[e * 12 + p], acc[p]);
    }
#pragma unroll
    for (int off = 16; off > 0; off >>= 1)
#pragma unroll
        for (int p = 0; p < 12; ++p) acc[p] += __shfl_down_sync(0xffffffffu, acc[p], off);
    if (lane == 0)
#pragma unroll
        for (int p = 0; p < 12; ++p) out[row * 12 + p] = acc[p] + bias[p];
}

__global__ __launch_bounds__(256) void copy4_kernel(const float4* __restrict__ s,
                                                    float4* __restrict__ d, int n4)
{
    const int i = blockIdx.x * blockDim.x + threadIdx.x;
    if (i < n4) d[i] = s[i];
}

// ---------------- launch ----------------
extern "C" void kernel_launch(void* const* d_in, const int* in_sizes, int n_in,
                              void* d_out, int out_size)
{
    const float* x       = (const float*)d_in[0];
    const float* A_hat   = (const float*)d_in[1];
    const float* tb1_w   = (const float*)d_in[2];
    const float* tb1_b   = (const float*)d_in[3];
    const float* theta1  = (const float*)d_in[4];
    const float* tb2_w   = (const float*)d_in[5];
    const float* tb2_b   = (const float*)d_in[6];
    const float* tb3_w   = (const float*)d_in[7];
    const float* tb3_b   = (const float*)d_in[8];
    const float* theta2  = (const float*)d_in[9];
    const float* tb4_w   = (const float*)d_in[10];
    const float* tb4_b   = (const float*)d_in[11];
    const float* tb5_w   = (const float*)d_in[12];
    const float* tb5_b   = (const float*)d_in[13];
    const float* fully_w = (const float*)d_in[14];
    const float* fully_b = (const float*)d_in[15];
    float* out = (float*)d_out;

    float *bufB, *bufC;
    __half *Ah, *Uh, *Ul, *Ch, *Xh, *Yh, *Wth, *Wtl;
    float2 *Wp, *bp;
    cudaGetSymbolAddress((void**)&bufB, g_bufB);
    cudaGetSymbolAddress((void**)&bufC, g_bufC);
    cudaGetSymbolAddress((void**)&Ah, g_Ah);
    cudaGetSymbolAddress((void**)&Uh, g_Uh);
    cudaGetSymbolAddress((void**)&Ul, g_Ul);
    cudaGetSymbolAddress((void**)&Ch, g_Ch);
    cudaGetSymbolAddress((void**)&Xh, g_Xh);
    cudaGetSymbolAddress((void**)&Yh, g_Yh);
    cudaGetSymbolAddress((void**)&Wth, g_Wth);
    cudaGetSymbolAddress((void**)&Wtl, g_Wtl);
    cudaGetSymbolAddress((void**)&Wp, g_Wp);
    cudaGetSymbolAddress((void**)&bp, g_bp);

    constexpr int WS = 128 * 192;
    constexpr int SMEM_G = 2 * 15360;   // 30720
    constexpr int SM_TB2 = 50176, SM_TB3 = 143360, SM_TB4 = 51328, SM_TB5 = 144512;
    cudaFuncSetAttribute(convmma_kernel<16, 22, 6, 4, false>, cudaFuncAttributeMaxDynamicSharedMemorySize, SM_TB2);
    cudaFuncSetAttribute(convmma_kernel<64, 20, 7, 4, false>, cudaFuncAttributeMaxDynamicSharedMemorySize, SM_TB3);
    cudaFuncSetAttribute(convmma_kernel<16, 18, 8, 4, false>, cudaFuncAttributeMaxDynamicSharedMemorySize, SM_TB4);
    cudaFuncSetAttribute(convmma_kernel<64, 16, 9, 4, true>,  cudaFuncAttributeMaxDynamicSharedMemorySize, SM_TB5);

    // prep
    packW_kernel<<<2, 256>>>(tb1_w, tb1_b, Wp, (float2*)bp + 0 * 64, 3 * 2 * 64);
    packWt_kernel<<<32, 256>>>(tb2_w, tb2_b, Wth + 0 * WS, Wtl + 0 * WS, (float2*)bp + 1 * 64, 16, 64);
    packWt_kernel<<<96, 256>>>(tb3_w, tb3_b, Wth + 1 * WS, Wtl + 1 * WS, (float2*)bp + 2 * 64, 64, 192);
    packWt_kernel<<<32, 256>>>(tb4_w, tb4_b, Wth + 2 * WS, Wtl + 2 * WS, (float2*)bp + 3 * 64, 16, 64);
    packWt_kernel<<<96, 256>>>(tb5_w, tb5_b, Wth + 3 * WS, Wtl + 3 * WS, (float2*)bp + 4 * 64, 64, 192);
    halfA_kernel<<<NNODE * NNODE / 256, 256>>>(A_hat, Ah);

    // block 1
    timeblock_kernel<2, 24><<<R_TOTAL / 2, dim3(64, 2)>>>(x, Wp, (float2*)bp + 0 * 64, theta1, bufC);
    tsplitU_kernel<352><<<dim3(64, 11, BATCH), 256>>>(bufC, Uh, Ul);
    gemm_mma_kernel<352><<<dim3(16, 11, BATCH), 256, SMEM_G>>>(Ah, Uh, Ul, Ch);
    convmma_kernel<16, 22, 6, 4, false><<<(R_TOTAL + 23) / 24, 256, SM_TB2>>>(
        Ch, Wth + 0 * WS, Wtl + 0 * WS, (float2*)bp + 1 * 64, nullptr, Xh);

    // block 2
    convmma_kernel<64, 20, 7, 4, false><<<(R_TOTAL + 27) / 28, 256, SM_TB3>>>(
        Xh, Wth + 1 * WS, Wtl + 1 * WS, (float2*)bp + 2 * 64, nullptr, Yh);
    theta_tsplit_kernel<<<dim3(256, 16), 256>>>(Yh, theta2, Uh, Ul);
    gemm_mma_kernel<288><<<dim3(16, 9, BATCH), 256, SMEM_G>>>(Ah, Uh, Ul, Ch);
    convmma_kernel<16, 18, 8, 4, false><<<R_TOTAL / 32, 256, SM_TB4>>>(
        Ch, Wth + 2 * WS, Wtl + 2 * WS, (float2*)bp + 3 * 64, nullptr, Xh);

    // head
    convmma_kernel<64, 16, 9, 4, true><<<(R_TOTAL + 35) / 36, 256, SM_TB5>>>(
        Xh, Wth + 3 * WS, Wtl + 3 * WS, (float2*)bp + 4 * 64, bufB, nullptr);
    fc_kernel<<<R_TOTAL / 8, dim3(32, 8)>>>(bufB, fully_w, fully_b, out);

    const int n4 = (NNODE * NNODE) / 4;
    copy4_kernel<<<(n4 + 255) / 256, 256>>>((const float4*)A_hat,
                                            (float4*)(out + (long)R_TOTAL * 12), n4);
}

// round 7
// speedup vs baseline: 3.7377x; 1.2650x over previous
#include <cuda_runtime.h>
#include <cuda_fp16.h>
#include <cstdint>
#include <math.h>

#define BATCH 16
#define NNODE 2048
#define R_TOTAL (BATCH * NNODE)

// ---------------- scratch (device globals) ----------------
__device__ __align__(16) float  g_bufB[R_TOTAL * 14 * 64];          // tb5 fp32 out
__device__ __align__(16) float  g_bufC[R_TOTAL * 22 * 16];          // u1 fp32
__device__ __align__(16) __half g_Ah[NNODE * NNODE];
__device__ __align__(16) __half g_Uh[(size_t)BATCH * 352 * NNODE];
__device__ __align__(16) __half g_Ch[(size_t)BATCH * 2048 * 352];   // einsum out
__device__ __align__(16) __half g_Xh[(size_t)R_TOTAL * 20 * 64];    // tb2/tb4 out
__device__ __align__(16) __half g_Yh[(size_t)R_TOTAL * 18 * 64];    // tb3 out
__device__ __align__(16) __half g_Wth[4 * 128 * 192];
__device__ __align__(16) float2 g_Wp[3 * 64 * 64];
__device__ __align__(16) float2 g_bp[5][64];

// ---------------- f32x2 helpers (tb1 scalar path) ----------------
__device__ __forceinline__ unsigned long long pk2(float lo, float hi) {
    unsigned long long r;
    asm("mov.b64 %0, {%1, %2};" : "=l"(r) : "f"(lo), "f"(hi));
    return r;
}
__device__ __forceinline__ void fma2(unsigned long long& d, unsigned long long a,
                                     unsigned long long b) {
    asm("fma.rn.f32x2 %0, %1, %2, %0;" : "+l"(d) : "l"(a), "l"(b));
}
__device__ __forceinline__ float2 upk(unsigned long long v) {
    float lo, hi;
    asm("mov.b64 {%0, %1}, %2;" : "=f"(lo), "=f"(hi) : "l"(v));
    return make_float2(lo, hi);
}

// ---------------- mma / cp.async helpers ----------------
__device__ __forceinline__ uint32_t smem_u32(const void* p) {
    uint32_t a;
    asm("{ .reg .u64 t; cvta.to.shared.u64 t, %1; cvt.u32.u64 %0, t; }" : "=r"(a) : "l"(p));
    return a;
}
#define CP16(sa, gp) asm volatile("cp.async.ca.shared.global [%0], [%1], 16;" \
    :: "r"(sa), "l"(gp) : "memory")
#define CPCOMMIT() asm volatile("cp.async.commit_group;" ::: "memory")
#define CPWAIT1()  asm volatile("cp.async.wait_group 1;" ::: "memory")
#define CPWAIT0()  asm volatile("cp.async.wait_group 0;" ::: "memory")
#define LDSM4(r, a) asm volatile( \
    "ldmatrix.sync.aligned.m8n8.x4.shared.b16 {%0,%1,%2,%3}, [%4];" \
    : "=r"((r)[0]), "=r"((r)[1]), "=r"((r)[2]), "=r"((r)[3]) : "r"(a))
__device__ __forceinline__ void mma_f16(float* c, const uint32_t* a,
                                        uint32_t b0, uint32_t b1) {
    asm volatile(
        "mma.sync.aligned.m16n8k16.row.col.f32.f16.f16.f32 "
        "{%0,%1,%2,%3}, {%4,%5,%6,%7}, {%8,%9}, {%0,%1,%2,%3};"
        : "+f"(c[0]), "+f"(c[1]), "+f"(c[2]), "+f"(c[3])
        : "r"(a[0]), "r"(a[1]), "r"(a[2]), "r"(a[3]), "r"(b0), "r"(b1));
}

// ---------------- prep kernels ----------------
__global__ __launch_bounds__(256) void packW_kernel(const float* __restrict__ W,
    const float* __restrict__ B3, float2* __restrict__ Wp, float2* __restrict__ bp, int n)
{
    int i = blockIdx.x * 256 + threadIdx.x;
    if (i < n) Wp[i] = make_float2(W[i] + W[n + i], W[2 * n + i]);
    if (i < 64) bp[i] = make_float2(B3[i] + B3[64 + i], B3[128 + i]);
}

// Wt[n][KM] fp16, n = 2c+g interleaved (temp/gate), zero-padded k >= 3*CIN
__global__ __launch_bounds__(256) void packWt_kernel(const float* __restrict__ W,
    const float* __restrict__ B3, __half* __restrict__ Wth,
    float2* __restrict__ bp, int CIN, int KM)
{
    const int K = 3 * CIN;
    int i = blockIdx.x * 256 + threadIdx.x;
    if (i < 128 * KM) {
        int n = i / KM, k = i % KM;
        float v = 0.0f;
        if (k < K) {
            int c = n >> 1, g = n & 1;
            int kk = k / CIN, cin = k % CIN;
            if (g == 0) v = W[(kk * CIN + cin) * 64 + c] + W[((3 + kk) * CIN + cin) * 64 + c];
            else        v = W[((6 + kk) * CIN + cin) * 64 + c];
        }
        Wth[i] = __float2half(v);
    }
    if (i < 64) bp[i] = make_float2(B3[i] + B3[64 + i], B3[128 + i]);
}

__global__ __launch_bounds__(256) void halfA_kernel(const float* __restrict__ A,
                                                    __half* __restrict__ H)
{
    int i = blockIdx.x * 256 + threadIdx.x;
    H[i] = __float2half(A[i]);
}

// U [z][2048][F] fp32 -> Ut fp16 [z][F][2048]
template <int F>
__global__ __launch_bounds__(256) void tsplitU_kernel(const float* __restrict__ U,
    __half* __restrict__ th)
{
    __shared__ float t[32][33];
    const int j0 = blockIdx.x * 32, f0 = blockIdx.y * 32, z = blockIdx.z;
    const int tx = threadIdx.x & 31, ty = threadIdx.x >> 5;
#pragma unroll
    for (int q = 0; q < 32; q += 8)
        t[ty + q][tx] = U[((size_t)z * 2048 + j0 + ty + q) * F + f0 + tx];
    __syncthreads();
#pragma unroll
    for (int q = 0; q < 32; q += 8) {
        size_t o = ((size_t)z * F + f0 + ty + q) * 2048 + j0 + tx;
        th[o] = __float2half(t[tx][ty + q]);
    }
}

// fused: u = Y @ theta2, transpose to fp16.  Y fp16 [R,18,64] -> U [z][288][2048]
__global__ __launch_bounds__(256) void theta_tsplit_kernel(
    const __half* __restrict__ Y, const float* __restrict__ theta,
    __half* __restrict__ Uh)
{
    __shared__ float ys[8 * 1156 + 4];
    __shared__ float th[64 * 16];
    const int tid = threadIdx.x;
    const int j0 = blockIdx.x * 8, z = blockIdx.y;
    const long rbase = (long)z * 2048 + j0;
    const uint4* src = (const uint4*)(Y + rbase * 1152);   // 8 halves / uint4, 144/row
    for (int i = tid; i < 8 * 144; i += 256) {
        int j = i / 144, q = i % 144;
        uint4 v = src[i];
        const __half2* hp = (const __half2*)&v;
        float* d = &ys[j * 1156 + q * 8];
#pragma unroll
        for (int e = 0; e < 4; ++e) {
            float2 f = __half22float2(hp[e]);
            d[2 * e] = f.x; d[2 * e + 1] = f.y;
        }
    }
    for (int i = tid; i < 1024; i += 256) th[i] = theta[i];
    __syncthreads();
    for (int o = tid; o < 288 * 8; o += 256) {
        int j = o & 7, f = o >> 3;
        int t = f >> 4, p = f & 15;
        const float* yr = &ys[j * 1156 + t * 64];
        float s = 0.0f;
#pragma unroll
        for (int m = 0; m < 64; ++m) s = fmaf(yr[m], th[m * 16 + p], s);
        Uh[((size_t)z * 288 + f) * 2048 + j0 + j] = __float2half(s);
    }
}

// ---------------- scalar timeblock (tb1, CIN=2) ----------------
template <int CIN, int TIN>
__global__ __launch_bounds__(128) void timeblock_kernel(
    const float* __restrict__ X, const float2* __restrict__ Wp,
    const float2* __restrict__ bp, const float* __restrict__ theta,
    float* __restrict__ Y)
{
    constexpr int TOUT = TIN - 2;
    constexpr int ROWS = 2;
    __shared__ __align__(16) float Xs[ROWS * TIN * CIN];
    __shared__ __align__(16) float Ys[ROWS * TOUT * 64];
    __shared__ __align__(16) float Ths[64 * 16];

    const int co = threadIdx.x, r = threadIdx.y;
    const int tid = r * 64 + co;
    const long row0 = (long)blockIdx.x * ROWS;
    {
        const float4* src = (const float4*)(X + row0 * (TIN * CIN));
        float4* dst = (float4*)Xs;
        for (int i = tid; i < ROWS * TIN * CIN / 4; i += 128) dst[i] = src[i];
    }
    for (int i = tid; i < 64 * 16; i += 128) Ths[i] = theta[i];
    __syncthreads();

    const float2 bb = bp[co];
    unsigned long long acc2[TOUT];
#pragma unroll
    for (int t = 0; t < TOUT; ++t) acc2[t] = pk2(bb.x, bb.y);

    const float* Xr = &Xs[r * TIN * CIN];
    for (int cin = 0; cin < CIN; ++cin) {
        unsigned long long xp[TIN];
#pragma unroll
        for (int t = 0; t < TIN; ++t) {
            const float v = Xr[t * CIN + cin];
            xp[t] = pk2(v, v);
        }
#pragma unroll
        for (int k = 0; k < 3; ++k) {
            const float2 wv = Wp[(k * CIN + cin) * 64 + co];
            const unsigned long long wp = pk2(wv.x, wv.y);
#pragma unroll
            for (int t = 0; t < TOUT; ++t) fma2(acc2[t], xp[t + k], wp);
        }
    }
#pragma unroll
    for (int t = 0; t < TOUT; ++t) {
        const float2 a = upk(acc2[t]);
        const float g = 1.0f / (1.0f + __expf(-a.y));
        float y = a.x * g;
        y = (y > 0.0f) ? y : 0.0f;
        Ys[(r * TOUT + t) * 64 + co] = y;
    }
    __syncthreads();
    for (int o = tid; o < ROWS * TOUT * 16; o += 128) {
        const int p = o & 15, t = (o >> 4) % TOUT, rr = o / (16 * TOUT);
        float s = 0.0f;
#pragma unroll
        for (int m = 0; m < 64; ++m)
            s = fmaf(Ys[(rr * TOUT + t) * 64 + m], Ths[m * 16 + p], s);
        Y[(row0 + rr) * (long)(TOUT * 16) + t * 16 + p] = s;
    }
}

// ---------------- conv-as-mma gated timeblock (single fp16) -----------------
// X fp16 [R, TIN*CIN]; W fp16 [128][KM] (n=2c+g interleaved); S slabs per CTA.
template <int CIN, int TIN, int G, int S, bool OUT32>
__global__ __launch_bounds__(256) void convmma_kernel(
    const __half* __restrict__ Xg, const __half* __restrict__ Whg,
    const float2* __restrict__ bp,
    float* __restrict__ Yf, __half* __restrict__ Yh)
{
    constexpr int TOUT = TIN - 2;
    constexpr int K = 3 * CIN;
    constexpr int KM = (K + 31) / 32 * 32;
    constexpr int KP = KM + 8;
    constexpr int TS = CIN + 8;
    constexpr int ROWEL = TIN * TS;
    constexpr int MROWS = G * TOUT;
    constexpr int XSZ = (G * ROWEL + 32) * 2;

    constexpr uint32_t XB0 = 0;
    constexpr uint32_t XB1 = XSZ;
    constexpr uint32_t WH = 2 * XSZ;
    constexpr uint32_t BIAS = WH + 128 * KP * 2;

    extern __shared__ __align__(128) char sm[];
    const uint32_t sb = smem_u32(sm);
    const int tid = threadIdx.x, w = tid >> 5, lane = tid & 31;
    const long base_r0 = (long)blockIdx.x * (G * S);

    // stage W (resident across slabs)
    constexpr int WCH = 128 * KM / 8;
    for (int i = tid; i < WCH; i += 256) {
        const int n = i / (KM / 8), kc = i % (KM / 8);
        CP16(sb + WH + (uint32_t)(n * KP + kc * 8) * 2, Whg + (size_t)n * KM + kc * 8);
    }

#define STAGE_X(bufoff, slab) do {                                             \
    const long r0_ = base_r0 + (long)(slab) * G;                               \
    for (int i = tid; i < G * TIN * CIN / 8; i += 256) {                       \
        const int r_ = i / (TIN * CIN / 8);                                    \
        const int rem_ = i % (TIN * CIN / 8);                                  \
        const int t_ = rem_ / (CIN / 8);                                       \
        const int c8_ = rem_ % (CIN / 8);                                      \
        long gr_ = r0_ + r_; if (gr_ >= R_TOTAL) gr_ = R_TOTAL - 1;            \
        CP16(sb + (bufoff) + (uint32_t)(r_ * ROWEL + t_ * TS + c8_ * 8) * 2,   \
             Xg + (size_t)gr_ * (TIN * CIN) + t_ * CIN + c8_ * 8);             \
    }                                                                          \
} while (0)

    STAGE_X(XB0, 0);
    CPCOMMIT();
    if (tid < 64) *(float2*)(sm + BIAS + tid * 8) = bp[tid];
    if (tid < 32) {
        ((__half*)(sm + XB0))[G * ROWEL + tid] = __float2half(0.0f);
        ((__half*)(sm + XB1))[G * ROWEL + tid] = __float2half(0.0f);
    }

    const int mA = w * 16 + (lane & 15);
    int rrA = mA / TOUT, ttA = mA % TOUT;
    if (mA >= MROWS) { rrA = 0; ttA = 0; }
    const uint32_t abase = (uint32_t)(rrA * ROWEL + ttA * TS) * 2;
    const int hi8 = (lane >> 4) * 8;
    const uint32_t bbase = (uint32_t)((lane & 7) * KP * 2 + (lane >> 3) * 16);
    const int rE = w * 16 + (lane >> 2);

    for (int s = 0; s < S; ++s) {
        if (s + 1 < S) {
            STAGE_X((s + 1) & 1 ? XB1 : XB0, s + 1);
            CPCOMMIT();
            CPWAIT1();
        } else {
            CPWAIT0();
        }
        __syncthreads();

        const uint32_t xb = sb + ((s & 1) ? XB1 : XB0);
        float acc[16][4];
#pragma unroll
        for (int nt = 0; nt < 16; ++nt)
#pragma unroll
            for (int q = 0; q < 4; ++q) acc[nt][q] = 0.0f;

#pragma unroll
        for (int kc = 0; kc < KM / 32; ++kc) {
            uint32_t ah[2][4];
#pragma unroll
            for (int s2 = 0; s2 < 2; ++s2) {
                const int e0 = (2 * kc + s2) * 16 + hi8;
                const uint32_t off = (uint32_t)((e0 / CIN) * TS + (e0 % CIN)) * 2;
                LDSM4(ah[s2], xb + abase + off);
            }
#pragma unroll
            for (int nt = 0; nt < 16; ++nt) {
                uint32_t bh[4];
                LDSM4(bh, sb + WH + bbase + (uint32_t)(nt * 8 * KP * 2 + kc * 64));
                mma_f16(acc[nt], ah[0], bh[0], bh[1]);
                mma_f16(acc[nt], ah[1], bh[2], bh[3]);
            }
        }

        const long r0s = base_r0 + (long)s * G;
#pragma unroll
        for (int hf = 0; hf < 2; ++hf) {
            const int m = rE + hf * 8;
            const int rr = m / TOUT, tt = m % TOUT;
            const long gr = r0s + rr;
            if (m < MROWS && gr < R_TOTAL) {
#pragma unroll
                for (int nt = 0; nt < 16; ++nt) {
                    const int c = nt * 4 + (lane & 3);
                    const float2 bb = *(const float2*)(sm + BIAS + c * 8);
                    const float temp = acc[nt][hf * 2 + 0] + bb.x;
                    const float gate = acc[nt][hf * 2 + 1] + bb.y;
                    const float gv = 1.0f / (1.0f + __expf(-gate));
                    float y = temp * gv;
                    y = (y > 0.0f) ? y : 0.0f;
                    const size_t o = ((size_t)gr * TOUT + tt) * 64 + c;
                    if (OUT32) Yf[o] = y;
                    else       Yh[o] = __float2half(y);
                }
            }
        }
        __syncthreads();
    }
#undef STAGE_X
}

// ---------------- einsum GEMM: Ch = fp16(relu(A @ U[z])), single-term -------
template <int F>
__global__ __launch_bounds__(256) void gemm_mma_kernel(
    const __half* __restrict__ Ah_g, const __half* __restrict__ Uh_g,
    __half* __restrict__ Ch_g)
{
    constexpr uint32_t BH = 128 * 80;        // 10240
    constexpr uint32_t STG = BH + 32 * 80;   // 12800 B/stage
    extern __shared__ __align__(128) char smc[];
    const uint32_t sb = smem_u32(smc);

    const int tid = threadIdx.x, w = tid >> 5, lane = tid & 31;
    const int m0 = blockIdx.x * 128, n0 = blockIdx.y * 32, z = blockIdx.z;

    const __half* Ab = Ah_g + (size_t)m0 * 2048;
    const __half* Bh = Uh_g + ((size_t)z * F + n0) * 2048;

    const int ra = tid >> 1;                     // 0..127 A row
    const uint32_t acb = (tid & 1) * 32;
    const int ace = (tid & 1) * 16;
    const int rbn = tid >> 3;                    // 0..31 B row
    const uint32_t cbB = (tid & 7) * 16;         // 8 chunks? 32 rows*4chunks=128, use tid<128
    const int ceB = (tid & 7) * 8;

#define LOAD_STAGE(buf, k0) do {                                               \
    const uint32_t st_ = sb + (buf) * STG;                                     \
    CP16(st_ + ra * 80 + acb,      Ab + (size_t)ra * 2048 + (k0) + ace);       \
    CP16(st_ + ra * 80 + acb + 16, Ab + (size_t)ra * 2048 + (k0) + ace + 8);   \
    if (rbn < 32 && (tid & 7) < 4)                                             \
        CP16(st_ + BH + rbn * 80 + cbB, Bh + (size_t)rbn * 2048 + (k0) + ceB); \
    CPCOMMIT();                                                                \
} while (0)

    float acc[4][4];
#pragma unroll
    for (int i = 0; i < 4; ++i)
#pragma unroll
        for (int j = 0; j < 4; ++j) acc[i][j] = 0.0f;

    LOAD_STAGE(0, 0);
    const uint32_t aoff = (uint32_t)((w * 16 + (lane & 15)) * 80 + (lane >> 4) * 16);
    const uint32_t boff2 = (uint32_t)((lane & 7) * 80 + (lane >> 3) * 16);

    for (int it = 0; it < 64; ++it) {
        if (it < 63) { LOAD_STAGE((it + 1) & 1, (it + 1) * 32); CPWAIT1(); }
        else CPWAIT0();
        __syncthreads();
        const uint32_t st = sb + (it & 1) * STG;
        uint32_t aF[2][4], bh[4][4];
        LDSM4(aF[0], st + aoff);
        LDSM4(aF[1], st + aoff + 32);
#pragma unroll
        for (int nt = 0; nt < 4; ++nt)
            LDSM4(bh[nt], st + BH + boff2 + nt * 8 * 80);
#pragma unroll
        for (int ks = 0; ks < 2; ++ks)
#pragma unroll
            for (int nt = 0; nt < 4; ++nt)
                mma_f16(acc[nt], aF[ks], bh[nt][2 * ks], bh[nt][2 * ks + 1]);
        __syncthreads();
    }

    const int mr = m0 + w * 16 + (lane >> 2);
    const int cc = n0 + 2 * (lane & 3);
    __half* H0 = Ch_g + ((size_t)z * 2048 + mr) * F + cc;
    __half* H1 = H0 + 8 * (size_t)F;
#pragma unroll
    for (int nt = 0; nt < 4; ++nt) {
        *(__half2*)(H0 + nt * 8) = __floats2half2_rn(fmaxf(acc[nt][0], 0.0f),
                                                     fmaxf(acc[nt][1], 0.0f));
        *(__half2*)(H1 + nt * 8) = __floats2half2_rn(fmaxf(acc[nt][2], 0.0f),
                                                     fmaxf(acc[nt][3], 0.0f));
    }
#undef LOAD_STAGE
}

// ---------------- FC + copy ----------------
__global__ __launch_bounds__(256) void fc_kernel(const float* __restrict__ X,
    const float* __restrict__ W, const float* __restrict__ bias, float* __restrict__ out)
{
    const int lane = threadIdx.x;
    const long row = (long)blockIdx.x * blockDim.y + threadIdx.y;
    const float* x = X + row * 896;
    float acc[12];
#pragma unroll
    for (int p = 0; p < 12; ++p) acc[p] = 0.0f;
    for (int e = lane; e < 896; e += 32) {
        const float xv = x[e];
#pragma unroll
        for (int p = 0; p < 12; ++p) acc[p] = fmaf(xv, W[e * 12 + p], acc[p]);
    }
#pragma unroll
    for (int off = 16; off > 0; off >>= 1)
#pragma unroll
        for (int p = 0; p < 12; ++p) acc[p] += __shfl_down_sync(0xffffffffu, acc[p], off);
    if (lane == 0)
#pragma unroll
        for (int p = 0; p < 12; ++p) out[row * 12 + p] = acc[p] + bias[p];
}

__global__ __launch_bounds__(256) void copy4_kernel(const float4* __restrict__ s,
                                                    float4* __restrict__ d, int n4)
{
    const int i = blockIdx.x * blockDim.x + threadIdx.x;
    if (i < n4) d[i] = s[i];
}

// ---------------- launch ----------------
extern "C" void kernel_launch(void* const* d_in, const int* in_sizes, int n_in,
                              void* d_out, int out_size)
{
    const float* x       = (const float*)d_in[0];
    const float* A_hat   = (const float*)d_in[1];
    const float* tb1_w   = (const float*)d_in[2];
    const float* tb1_b   = (const float*)d_in[3];
    const float* theta1  = (const float*)d_in[4];
    const float* tb2_w   = (const float*)d_in[5];
    const float* tb2_b   = (const float*)d_in[6];
    const float* tb3_w   = (const float*)d_in[7];
    const float* tb3_b   = (const float*)d_in[8];
    const float* theta2  = (const float*)d_in[9];
    const float* tb4_w   = (const float*)d_in[10];
    const float* tb4_b   = (const float*)d_in[11];
    const float* tb5_w   = (const float*)d_in[12];
    const float* tb5_b   = (const float*)d_in[13];
    const float* fully_w = (const float*)d_in[14];
    const float* fully_b = (const float*)d_in[15];
    float* out = (float*)d_out;

    float *bufB, *bufC;
    __half *Ah, *Uh, *Ch, *Xh, *Yh, *Wth;
    float2 *Wp, *bp;
    cudaGetSymbolAddress((void**)&bufB, g_bufB);
    cudaGetSymbolAddress((void**)&bufC, g_bufC);
    cudaGetSymbolAddress((void**)&Ah, g_Ah);
    cudaGetSymbolAddress((void**)&Uh, g_Uh);
    cudaGetSymbolAddress((void**)&Ch, g_Ch);
    cudaGetSymbolAddress((void**)&Xh, g_Xh);
    cudaGetSymbolAddress((void**)&Yh, g_Yh);
    cudaGetSymbolAddress((void**)&Wth, g_Wth);
    cudaGetSymbolAddress((void**)&Wp, g_Wp);
    cudaGetSymbolAddress((void**)&bp, g_bp);

    constexpr int WS = 128 * 192;
    constexpr int SMEM_G = 2 * 12800;   // 25600
    constexpr int SM_TB2 = 32768, SM_TB3 = 93184, SM_TB4 = 33920, SM_TB5 = 94336;
    cudaFuncSetAttribute(convmma_kernel<16, 22, 6, 4, false>, cudaFuncAttributeMaxDynamicSharedMemorySize, SM_TB2);
    cudaFuncSetAttribute(convmma_kernel<64, 20, 7, 4, false>, cudaFuncAttributeMaxDynamicSharedMemorySize, SM_TB3);
    cudaFuncSetAttribute(convmma_kernel<16, 18, 8, 4, false>, cudaFuncAttributeMaxDynamicSharedMemorySize, SM_TB4);
    cudaFuncSetAttribute(convmma_kernel<64, 16, 9, 4, true>,  cudaFuncAttributeMaxDynamicSharedMemorySize, SM_TB5);

    // prep
    packW_kernel<<<2, 256>>>(tb1_w, tb1_b, Wp, (float2*)bp + 0 * 64, 3 * 2 * 64);
    packWt_kernel<<<32, 256>>>(tb2_w, tb2_b, Wth + 0 * WS, (float2*)bp + 1 * 64, 16, 64);
    packWt_kernel<<<96, 256>>>(tb3_w, tb3_b, Wth + 1 * WS, (float2*)bp + 2 * 64, 64, 192);
    packWt_kernel<<<32, 256>>>(tb4_w, tb4_b, Wth + 2 * WS, (float2*)bp + 3 * 64, 16, 64);
    packWt_kernel<<<96, 256>>>(tb5_w, tb5_b, Wth + 3 * WS, (float2*)bp + 4 * 64, 64, 192);
    halfA_kernel<<<NNODE * NNODE / 256, 256>>>(A_hat, Ah);

    // block 1
    timeblock_kernel<2, 24><<<R_TOTAL / 2, dim3(64, 2)>>>(x, Wp, (float2*)bp + 0 * 64, theta1, bufC);
    tsplitU_kernel<352><<<dim3(64, 11, BATCH), 256>>>(bufC, Uh);
    gemm_mma_kernel<352><<<dim3(16, 11, BATCH), 256, SMEM_G>>>(Ah, Uh, Ch);
    convmma_kernel<16, 22, 6, 4, false><<<(R_TOTAL + 23) / 24, 256, SM_TB2>>>(
        Ch, Wth + 0 * WS, (float2*)bp + 1 * 64, nullptr, Xh);

    // block 2
    convmma_kernel<64, 20, 7, 4, false><<<(R_TOTAL + 27) / 28, 256, SM_TB3>>>(
        Xh, Wth + 1 * WS, (float2*)bp + 2 * 64, nullptr, Yh);
    theta_tsplit_kernel<<<dim3(256, 16), 256>>>(Yh, theta2, Uh);
    gemm_mma_kernel<288><<<dim3(16, 9, BATCH), 256, SMEM_G>>>(Ah, Uh, Ch);
    convmma_kernel<16, 18, 8, 4, false><<<R_TOTAL / 32, 256, SM_TB4>>>(
        Ch, Wth + 2 * WS, (float2*)bp + 3 * 64, nullptr, Xh);

    // head
    convmma_kernel<64, 16, 9, 4, true><<<(R_TOTAL + 35) / 36, 256, SM_TB5>>>(
        Xh, Wth + 3 * WS, (float2*)bp + 4 * 64, bufB, nullptr);
    fc_kernel<<<R_TOTAL / 8, dim3(32, 8)>>>(bufB, fully_w, fully_b, out);

    const int n4 = (NNODE * NNODE) / 4;
    copy4_kernel<<<(n4 + 255) / 256, 256>>>((const float4*)A_hat,
                                            (float4*)(out + (long)R_TOTAL * 12), n4);
}

// round 8
// speedup vs baseline: 3.8834x; 1.0390x over previous
#include <cuda_runtime.h>
#include <cuda_fp16.h>
#include <cstdint>
#include <math.h>

#define BATCH 16
#define NNODE 2048
#define R_TOTAL (BATCH * NNODE)

// ---------------- scratch (device globals) ----------------
__device__ __align__(16) float  g_bufC[R_TOTAL * 22 * 16];          // u1 fp32
__device__ __align__(16) __half g_Ah[NNODE * NNODE];
__device__ __align__(16) __half g_Uh[(size_t)BATCH * 352 * NNODE];
__device__ __align__(16) __half g_Ch[(size_t)BATCH * 2048 * 352];   // einsum out
__device__ __align__(16) __half g_Xh[(size_t)R_TOTAL * 20 * 64];    // tb2/tb4 out
__device__ __align__(16) __half g_Yh[(size_t)R_TOTAL * 18 * 64];    // tb3 / tb5 out
__device__ __align__(16) __half g_Wth[4 * 128 * 192];
__device__ __align__(16) float2 g_Wp[3 * 64 * 64];
__device__ __align__(16) float2 g_bp[5][64];

// ---------------- f32x2 helpers (tb1 scalar path) ----------------
__device__ __forceinline__ unsigned long long pk2(float lo, float hi) {
    unsigned long long r;
    asm("mov.b64 %0, {%1, %2};" : "=l"(r) : "f"(lo), "f"(hi));
    return r;
}
__device__ __forceinline__ void fma2(unsigned long long& d, unsigned long long a,
                                     unsigned long long b) {
    asm("fma.rn.f32x2 %0, %1, %2, %0;" : "+l"(d) : "l"(a), "l"(b));
}
__device__ __forceinline__ float2 upk(unsigned long long v) {
    float lo, hi;
    asm("mov.b64 {%0, %1}, %2;" : "=f"(lo), "=f"(hi) : "l"(v));
    return make_float2(lo, hi);
}

// ---------------- mma / cp.async helpers ----------------
__device__ __forceinline__ uint32_t smem_u32(const void* p) {
    uint32_t a;
    asm("{ .reg .u64 t; cvta.to.shared.u64 t, %1; cvt.u32.u64 %0, t; }" : "=r"(a) : "l"(p));
    return a;
}
#define CP16(sa, gp) asm volatile("cp.async.ca.shared.global [%0], [%1], 16;" \
    :: "r"(sa), "l"(gp) : "memory")
#define CPCOMMIT() asm volatile("cp.async.commit_group;" ::: "memory")
#define CPWAIT1()  asm volatile("cp.async.wait_group 1;" ::: "memory")
#define CPWAIT0()  asm volatile("cp.async.wait_group 0;" ::: "memory")
#define LDSM4(r, a) asm volatile( \
    "ldmatrix.sync.aligned.m8n8.x4.shared.b16 {%0,%1,%2,%3}, [%4];" \
    : "=r"((r)[0]), "=r"((r)[1]), "=r"((r)[2]), "=r"((r)[3]) : "r"(a))
__device__ __forceinline__ void mma_f16(float* c, const uint32_t* a,
                                        uint32_t b0, uint32_t b1) {
    asm volatile(
        "mma.sync.aligned.m16n8k16.row.col.f32.f16.f16.f32 "
        "{%0,%1,%2,%3}, {%4,%5,%6,%7}, {%8,%9}, {%0,%1,%2,%3};"
        : "+f"(c[0]), "+f"(c[1]), "+f"(c[2]), "+f"(c[3])
        : "r"(a[0]), "r"(a[1]), "r"(a[2]), "r"(a[3]), "r"(b0), "r"(b1));
}

// ---------------- prep kernels ----------------
__global__ __launch_bounds__(256) void packW_kernel(const float* __restrict__ W,
    const float* __restrict__ B3, float2* __restrict__ Wp, float2* __restrict__ bp, int n)
{
    int i = blockIdx.x * 256 + threadIdx.x;
    if (i < n) Wp[i] = make_float2(W[i] + W[n + i], W[2 * n + i]);
    if (i < 64) bp[i] = make_float2(B3[i] + B3[64 + i], B3[128 + i]);
}

// Wt[n][KM] fp16, n = 2c+g interleaved (temp/gate), zero-padded k >= 3*CIN
__global__ __launch_bounds__(256) void packWt_kernel(const float* __restrict__ W,
    const float* __restrict__ B3, __half* __restrict__ Wth,
    float2* __restrict__ bp, int CIN, int KM)
{
    const int K = 3 * CIN;
    int i = blockIdx.x * 256 + threadIdx.x;
    if (i < 128 * KM) {
        int n = i / KM, k = i % KM;
        float v = 0.0f;
        if (k < K) {
            int c = n >> 1, g = n & 1;
            int kk = k / CIN, cin = k % CIN;
            if (g == 0) v = W[(kk * CIN + cin) * 64 + c] + W[((3 + kk) * CIN + cin) * 64 + c];
            else        v = W[((6 + kk) * CIN + cin) * 64 + c];
        }
        Wth[i] = __float2half(v);
    }
    if (i < 64) bp[i] = make_float2(B3[i] + B3[64 + i], B3[128 + i]);
}

__global__ __launch_bounds__(256) void halfA_kernel(const float* __restrict__ A,
                                                    __half* __restrict__ H)
{
    int i = blockIdx.x * 256 + threadIdx.x;
    H[i] = __float2half(A[i]);
}

// U [z][2048][F] fp32 -> Ut fp16 [z][F][2048]
template <int F>
__global__ __launch_bounds__(256) void tsplitU_kernel(const float* __restrict__ U,
    __half* __restrict__ th)
{
    __shared__ float t[32][33];
    const int j0 = blockIdx.x * 32, f0 = blockIdx.y * 32, z = blockIdx.z;
    const int tx = threadIdx.x & 31, ty = threadIdx.x >> 5;
#pragma unroll
    for (int q = 0; q < 32; q += 8)
        t[ty + q][tx] = U[((size_t)z * 2048 + j0 + ty + q) * F + f0 + tx];
    __syncthreads();
#pragma unroll
    for (int q = 0; q < 32; q += 8) {
        size_t o = ((size_t)z * F + f0 + ty + q) * 2048 + j0 + tx;
        th[o] = __float2half(t[tx][ty + q]);
    }
}

// fused: u = Y @ theta2, transpose to fp16.  Y fp16 [R,18,64] -> U [z][288][2048]
__global__ __launch_bounds__(256) void theta_tsplit_kernel(
    const __half* __restrict__ Y, const float* __restrict__ theta,
    __half* __restrict__ Uh)
{
    __shared__ float ys[8 * 1156 + 4];
    __shared__ float th[64 * 16];
    const int tid = threadIdx.x;
    const int j0 = blockIdx.x * 8, z = blockIdx.y;
    const long rbase = (long)z * 2048 + j0;
    const uint4* src = (const uint4*)(Y + rbase * 1152);   // 8 halves / uint4, 144/row
    for (int i = tid; i < 8 * 144; i += 256) {
        int j = i / 144, q = i % 144;
        uint4 v = src[i];
        const __half2* hp = (const __half2*)&v;
        float* d = &ys[j * 1156 + q * 8];
#pragma unroll
        for (int e = 0; e < 4; ++e) {
            float2 f = __half22float2(hp[e]);
            d[2 * e] = f.x; d[2 * e + 1] = f.y;
        }
    }
    for (int i = tid; i < 1024; i += 256) th[i] = theta[i];
    __syncthreads();
    for (int o = tid; o < 288 * 8; o += 256) {
        int j = o & 7, f = o >> 3;
        int t = f >> 4, p = f & 15;
        const float* yr = &ys[j * 1156 + t * 64];
        float s = 0.0f;
#pragma unroll
        for (int m = 0; m < 64; ++m) s = fmaf(yr[m], th[m * 16 + p], s);
        Uh[((size_t)z * 288 + f) * 2048 + j0 + j] = __float2half(s);
    }
}

// ---------------- scalar timeblock (tb1, CIN=2) ----------------
template <int CIN, int TIN>
__global__ __launch_bounds__(128) void timeblock_kernel(
    const float* __restrict__ X, const float2* __restrict__ Wp,
    const float2* __restrict__ bp, const float* __restrict__ theta,
    float* __restrict__ Y)
{
    constexpr int TOUT = TIN - 2;
    constexpr int ROWS = 2;
    __shared__ __align__(16) float Xs[ROWS * TIN * CIN];
    __shared__ __align__(16) float Ys[ROWS * TOUT * 64];
    __shared__ __align__(16) float Ths[64 * 16];

    const int co = threadIdx.x, r = threadIdx.y;
    const int tid = r * 64 + co;
    const long row0 = (long)blockIdx.x * ROWS;
    {
        const float4* src = (const float4*)(X + row0 * (TIN * CIN));
        float4* dst = (float4*)Xs;
        for (int i = tid; i < ROWS * TIN * CIN / 4; i += 128) dst[i] = src[i];
    }
    for (int i = tid; i < 64 * 16; i += 128) Ths[i] = theta[i];
    __syncthreads();

    const float2 bb = bp[co];
    unsigned long long acc2[TOUT];
#pragma unroll
    for (int t = 0; t < TOUT; ++t) acc2[t] = pk2(bb.x, bb.y);

    const float* Xr = &Xs[r * TIN * CIN];
    for (int cin = 0; cin < CIN; ++cin) {
        unsigned long long xp[TIN];
#pragma unroll
        for (int t = 0; t < TIN; ++t) {
            const float v = Xr[t * CIN + cin];
            xp[t] = pk2(v, v);
        }
#pragma unroll
        for (int k = 0; k < 3; ++k) {
            const float2 wv = Wp[(k * CIN + cin) * 64 + co];
            const unsigned long long wp = pk2(wv.x, wv.y);
#pragma unroll
            for (int t = 0; t < TOUT; ++t) fma2(acc2[t], xp[t + k], wp);
        }
    }
#pragma unroll
    for (int t = 0; t < TOUT; ++t) {
        const float2 a = upk(acc2[t]);
        const float g = 1.0f / (1.0f + __expf(-a.y));
        float y = a.x * g;
        y = (y > 0.0f) ? y : 0.0f;
        Ys[(r * TOUT + t) * 64 + co] = y;
    }
    __syncthreads();
    for (int o = tid; o < ROWS * TOUT * 16; o += 128) {
        const int p = o & 15, t = (o >> 4) % TOUT, rr = o / (16 * TOUT);
        float s = 0.0f;
#pragma unroll
        for (int m = 0; m < 64; ++m)
            s = fmaf(Ys[(rr * TOUT + t) * 64 + m], Ths[m * 16 + p], s);
        Y[(row0 + rr) * (long)(TOUT * 16) + t * 16 + p] = s;
    }
}

// ---------------- conv-as-mma gated timeblock (single fp16) -----------------
template <int CIN, int TIN, int G, int S, bool OUT32>
__global__ __launch_bounds__(256) void convmma_kernel(
    const __half* __restrict__ Xg, const __half* __restrict__ Whg,
    const float2* __restrict__ bp,
    float* __restrict__ Yf, __half* __restrict__ Yh)
{
    constexpr int TOUT = TIN - 2;
    constexpr int K = 3 * CIN;
    constexpr int KM = (K + 31) / 32 * 32;
    constexpr int KP = KM + 8;
    constexpr int TS = CIN + 8;
    constexpr int ROWEL = TIN * TS;
    constexpr int MROWS = G * TOUT;
    constexpr int XSZ = (G * ROWEL + 32) * 2;

    constexpr uint32_t XB0 = 0;
    constexpr uint32_t XB1 = XSZ;
    constexpr uint32_t WH = 2 * XSZ;
    constexpr uint32_t BIAS = WH + 128 * KP * 2;

    extern __shared__ __align__(128) char sm[];
    const uint32_t sb = smem_u32(sm);
    const int tid = threadIdx.x, w = tid >> 5, lane = tid & 31;
    const long base_r0 = (long)blockIdx.x * (G * S);

    // stage W (resident across slabs)
    constexpr int WCH = 128 * KM / 8;
    for (int i = tid; i < WCH; i += 256) {
        const int n = i / (KM / 8), kc = i % (KM / 8);
        CP16(sb + WH + (uint32_t)(n * KP + kc * 8) * 2, Whg + (size_t)n * KM + kc * 8);
    }

#define STAGE_X(bufoff, slab) do {                                             \
    const long r0_ = base_r0 + (long)(slab) * G;                               \
    for (int i = tid; i < G * TIN * CIN / 8; i += 256) {                       \
        const int r_ = i / (TIN * CIN / 8);                                    \
        const int rem_ = i % (TIN * CIN / 8);                                  \
        const int t_ = rem_ / (CIN / 8);                                       \
        const int c8_ = rem_ % (CIN / 8);                                      \
        long gr_ = r0_ + r_; if (gr_ >= R_TOTAL) gr_ = R_TOTAL - 1;            \
        CP16(sb + (bufoff) + (uint32_t)(r_ * ROWEL + t_ * TS + c8_ * 8) * 2,   \
             Xg + (size_t)gr_ * (TIN * CIN) + t_ * CIN + c8_ * 8);             \
    }                                                                          \
} while (0)

    STAGE_X(XB0, 0);
    CPCOMMIT();
    if (tid < 64) *(float2*)(sm + BIAS + tid * 8) = bp[tid];
    if (tid < 32) {
        ((__half*)(sm + XB0))[G * ROWEL + tid] = __float2half(0.0f);
        ((__half*)(sm + XB1))[G * ROWEL + tid] = __float2half(0.0f);
    }

    const int mA = w * 16 + (lane & 15);
    int rrA = mA / TOUT, ttA = mA % TOUT;
    if (mA >= MROWS) { rrA = 0; ttA = 0; }
    const uint32_t abase = (uint32_t)(rrA * ROWEL + ttA * TS) * 2;
    const int hi8 = (lane >> 4) * 8;
    const uint32_t bbase = (uint32_t)((lane & 7) * KP * 2 + (lane >> 3) * 16);
    const int rE = w * 16 + (lane >> 2);

    for (int s = 0; s < S; ++s) {
        if (s + 1 < S) {
            STAGE_X((s + 1) & 1 ? XB1 : XB0, s + 1);
            CPCOMMIT();
            CPWAIT1();
        } else {
            CPWAIT0();
        }
        __syncthreads();

        const uint32_t xb = sb + ((s & 1) ? XB1 : XB0);
        float acc[16][4];
#pragma unroll
        for (int nt = 0; nt < 16; ++nt)
#pragma unroll
            for (int q = 0; q < 4; ++q) acc[nt][q] = 0.0f;

#pragma unroll
        for (int kc = 0; kc < KM / 32; ++kc) {
            uint32_t ah[2][4];
#pragma unroll
            for (int s2 = 0; s2 < 2; ++s2) {
                const int e0 = (2 * kc + s2) * 16 + hi8;
                const uint32_t off = (uint32_t)((e0 / CIN) * TS + (e0 % CIN)) * 2;
                LDSM4(ah[s2], xb + abase + off);
            }
#pragma unroll
            for (int nt = 0; nt < 16; ++nt) {
                uint32_t bh[4];
                LDSM4(bh, sb + WH + bbase + (uint32_t)(nt * 8 * KP * 2 + kc * 64));
                mma_f16(acc[nt], ah[0], bh[0], bh[1]);
                mma_f16(acc[nt], ah[1], bh[2], bh[3]);
            }
        }

        const long r0s = base_r0 + (long)s * G;
#pragma unroll
        for (int hf = 0; hf < 2; ++hf) {
            const int m = rE + hf * 8;
            const int rr = m / TOUT, tt = m % TOUT;
            const long gr = r0s + rr;
            if (m < MROWS && gr < R_TOTAL) {
#pragma unroll
                for (int nt = 0; nt < 16; ++nt) {
                    const int c = nt * 4 + (lane & 3);
                    const float2 bb = *(const float2*)(sm + BIAS + c * 8);
                    const float temp = acc[nt][hf * 2 + 0] + bb.x;
                    const float gate = acc[nt][hf * 2 + 1] + bb.y;
                    const float gv = 1.0f / (1.0f + __expf(-gate));
                    float y = temp * gv;
                    y = (y > 0.0f) ? y : 0.0f;
                    const size_t o = ((size_t)gr * TOUT + tt) * 64 + c;
                    if (OUT32) Yf[o] = y;
                    else       Yh[o] = __float2half(y);
                }
            }
        }
        __syncthreads();
    }
#undef STAGE_X
}

// ------- einsum GEMM (z-folded): Ch[z][2048][F] = fp16(relu(A @ U)) ---------
// A fp16 [2048,2048]; U fp16 rows n=z*F+f over [16*F][2048]; BM=128, BN=64.
template <int F>
__global__ __launch_bounds__(256) void gemm_mma_kernel(
    const __half* __restrict__ Ah_g, const __half* __restrict__ Uh_g,
    __half* __restrict__ Ch_g)
{
    constexpr uint32_t BH = 128 * 80;        // 10240
    constexpr uint32_t STG = BH + 64 * 80;   // 15360 B/stage
    extern __shared__ __align__(128) char smc[];
    const uint32_t sb = smem_u32(smc);

    const int tid = threadIdx.x, w = tid >> 5, lane = tid & 31;
    const int m0 = blockIdx.x * 128, n0 = blockIdx.y * 64;

    const __half* Ab = Ah_g + (size_t)m0 * 2048;
    const __half* Bb = Uh_g + (size_t)n0 * 2048;

    const int ra = tid >> 1;                 // 0..127 A row
    const uint32_t acb = (tid & 1) * 32;
    const int ace = (tid & 1) * 16;
    const int rb = tid >> 2;                 // 0..63 B row
    const uint32_t bcb = (tid & 3) * 16;
    const int bce = (tid & 3) * 8;

#define LOAD_STAGE(buf, k0) do {                                               \
    const uint32_t st_ = sb + (buf) * STG;                                     \
    CP16(st_ + ra * 80 + acb,      Ab + (size_t)ra * 2048 + (k0) + ace);       \
    CP16(st_ + ra * 80 + acb + 16, Ab + (size_t)ra * 2048 + (k0) + ace + 8);   \
    CP16(st_ + BH + rb * 80 + bcb, Bb + (size_t)rb * 2048 + (k0) + bce);       \
    CPCOMMIT();                                                                \
} while (0)

    float acc[8][4];
#pragma unroll
    for (int i = 0; i < 8; ++i)
#pragma unroll
        for (int j = 0; j < 4; ++j) acc[i][j] = 0.0f;

    LOAD_STAGE(0, 0);
    const uint32_t aoff = (uint32_t)((w * 16 + (lane & 15)) * 80 + (lane >> 4) * 16);
    const uint32_t boff2 = (uint32_t)((lane & 7) * 80 + (lane >> 3) * 16);

    for (int it = 0; it < 64; ++it) {
        if (it < 63) { LOAD_STAGE((it + 1) & 1, (it + 1) * 32); CPWAIT1(); }
        else CPWAIT0();
        __syncthreads();
        const uint32_t st = sb + (it & 1) * STG;
        uint32_t aF[2][4];
        LDSM4(aF[0], st + aoff);
        LDSM4(aF[1], st + aoff + 32);
#pragma unroll
        for (int nt = 0; nt < 8; ++nt) {
            uint32_t bh[4];
            LDSM4(bh, st + BH + boff2 + nt * 8 * 80);
            mma_f16(acc[nt], aF[0], bh[0], bh[1]);
            mma_f16(acc[nt], aF[1], bh[2], bh[3]);
        }
        __syncthreads();
    }

    const int mr = m0 + w * 16 + (lane >> 2);
    const int cbase = 2 * (lane & 3);
#pragma unroll
    for (int nt = 0; nt < 8; ++nt) {
        const int n = n0 + nt * 8 + cbase;
        const int z = n / F, f = n - z * F;
        __half* H0 = Ch_g + ((size_t)z * 2048 + mr) * F + f;
        *(__half2*)H0 = __floats2half2_rn(fmaxf(acc[nt][0], 0.0f),
                                          fmaxf(acc[nt][1], 0.0f));
        *(__half2*)(H0 + 8 * (size_t)F) = __floats2half2_rn(fmaxf(acc[nt][2], 0.0f),
                                                            fmaxf(acc[nt][3], 0.0f));
    }
#undef LOAD_STAGE
}

// ---------------- FC (fp16 input) + copy ----------------
__global__ __launch_bounds__(256) void fc_kernel(const __half* __restrict__ X,
    const float* __restrict__ W, const float* __restrict__ bias, float* __restrict__ out)
{
    const int lane = threadIdx.x;
    const long row = (long)blockIdx.x * blockDim.y + threadIdx.y;
    const __half2* x2 = (const __half2*)(X + row * 896);
    float acc[12];
#pragma unroll
    for (int p = 0; p < 12; ++p) acc[p] = 0.0f;
    for (int e2 = lane; e2 < 448; e2 += 32) {
        const float2 f = __half22float2(x2[e2]);
        const float* w0 = W + (size_t)(2 * e2) * 12;
#pragma unroll
        for (int p = 0; p < 12; ++p)
            acc[p] = fmaf(f.x, w0[p], fmaf(f.y, w0[12 + p], acc[p]));
    }
#pragma unroll
    for (int off = 16; off > 0; off >>= 1)
#pragma unroll
        for (int p = 0; p < 12; ++p) acc[p] += __shfl_down_sync(0xffffffffu, acc[p], off);
    if (lane == 0)
#pragma unroll
        for (int p = 0; p < 12; ++p) out[row * 12 + p] = acc[p] + bias[p];
}

__global__ __launch_bounds__(256) void copy4_kernel(const float4* __restrict__ s,
                                                    float4* __restrict__ d, int n4)
{
    const int i = blockIdx.x * blockDim.x + threadIdx.x;
    if (i < n4) d[i] = s[i];
}

// ---------------- launch ----------------
extern "C" void kernel_launch(void* const* d_in, const int* in_sizes, int n_in,
                              void* d_out, int out_size)
{
    const float* x       = (const float*)d_in[0];
    const float* A_hat   = (const float*)d_in[1];
    const float* tb1_w   = (const float*)d_in[2];
    const float* tb1_b   = (const float*)d_in[3];
    const float* theta1  = (const float*)d_in[4];
    const float* tb2_w   = (const float*)d_in[5];
    const float* tb2_b   = (const float*)d_in[6];
    const float* tb3_w   = (const float*)d_in[7];
    const float* tb3_b   = (const float*)d_in[8];
    const float* theta2  = (const float*)d_in[9];
    const float* tb4_w   = (const float*)d_in[10];
    const float* tb4_b   = (const float*)d_in[11];
    const float* tb5_w   = (const float*)d_in[12];
    const float* tb5_b   = (const float*)d_in[13];
    const float* fully_w = (const float*)d_in[14];
    const float* fully_b = (const float*)d_in[15];
    float* out = (float*)d_out;

    float *bufC;
    __half *Ah, *Uh, *Ch, *Xh, *Yh, *Wth;
    float2 *Wp, *bp;
    cudaGetSymbolAddress((void**)&bufC, g_bufC);
    cudaGetSymbolAddress((void**)&Ah, g_Ah);
    cudaGetSymbolAddress((void**)&Uh, g_Uh);
    cudaGetSymbolAddress((void**)&Ch, g_Ch);
    cudaGetSymbolAddress((void**)&Xh, g_Xh);
    cudaGetSymbolAddress((void**)&Yh, g_Yh);
    cudaGetSymbolAddress((void**)&Wth, g_Wth);
    cudaGetSymbolAddress((void**)&Wp, g_Wp);
    cudaGetSymbolAddress((void**)&bp, g_bp);

    constexpr int WS = 128 * 192;
    constexpr int SMEM_G = 2 * 15360;   // 30720
    constexpr int SM_TB2 = 32768, SM_TB3 = 93184, SM_TB4 = 33920, SM_TB5 = 94336;
    cudaFuncSetAttribute(convmma_kernel<16, 22, 6, 8, false>, cudaFuncAttributeMaxDynamicSharedMemorySize, SM_TB2);
    cudaFuncSetAttribute(convmma_kernel<64, 20, 7, 8, false>, cudaFuncAttributeMaxDynamicSharedMemorySize, SM_TB3);
    cudaFuncSetAttribute(convmma_kernel<16, 18, 8, 8, false>, cudaFuncAttributeMaxDynamicSharedMemorySize, SM_TB4);
    cudaFuncSetAttribute(convmma_kernel<64, 16, 9, 8, false>, cudaFuncAttributeMaxDynamicSharedMemorySize, SM_TB5);

    // prep
    packW_kernel<<<2, 256>>>(tb1_w, tb1_b, Wp, (float2*)bp + 0 * 64, 3 * 2 * 64);
    packWt_kernel<<<32, 256>>>(tb2_w, tb2_b, Wth + 0 * WS, (float2*)bp + 1 * 64, 16, 64);
    packWt_kernel<<<96, 256>>>(tb3_w, tb3_b, Wth + 1 * WS, (float2*)bp + 2 * 64, 64, 192);
    packWt_kernel<<<32, 256>>>(tb4_w, tb4_b, Wth + 2 * WS, (float2*)bp + 3 * 64, 16, 64);
    packWt_kernel<<<96, 256>>>(tb5_w, tb5_b, Wth + 3 * WS, (float2*)bp + 4 * 64, 64, 192);
    halfA_kernel<<<NNODE * NNODE / 256, 256>>>(A_hat, Ah);

    // block 1
    timeblock_kernel<2, 24><<<R_TOTAL / 2, dim3(64, 2)>>>(x, Wp, (float2*)bp + 0 * 64, theta1, bufC);
    tsplitU_kernel<352><<<dim3(64, 11, BATCH), 256>>>(bufC, Uh);
    gemm_mma_kernel<352><<<dim3(16, (BATCH * 352) / 64), 256, SMEM_G>>>(Ah, Uh, Ch);
    convmma_kernel<16, 22, 6, 8, false><<<(R_TOTAL + 47) / 48, 256, SM_TB2>>>(
        Ch, Wth + 0 * WS, (float2*)bp + 1 * 64, nullptr, Xh);

    // block 2
    convmma_kernel<64, 20, 7, 8, false><<<(R_TOTAL + 55) / 56, 256, SM_TB3>>>(
        Xh, Wth + 1 * WS, (float2*)bp + 2 * 64, nullptr, Yh);
    theta_tsplit_kernel<<<dim3(256, 16), 256>>>(Yh, theta2, Uh);
    gemm_mma_kernel<288><<<dim3(16, (BATCH * 288) / 64), 256, SMEM_G>>>(Ah, Uh, Ch);
    convmma_kernel<16, 18, 8, 8, false><<<R_TOTAL / 64, 256, SM_TB4>>>(
        Ch, Wth + 2 * WS, (float2*)bp + 3 * 64, nullptr, Xh);

    // head (tb5 -> fp16 into Yh, FC reads fp16)
    convmma_kernel<64, 16, 9, 8, false><<<(R_TOTAL + 71) / 72, 256, SM_TB5>>>(
        Xh, Wth + 3 * WS, (float2*)bp + 4 * 64, nullptr, Yh);
    fc_kernel<<<R_TOTAL / 8, dim3(32, 8)>>>(Yh, fully_w, fully_b, out);

    const int n4 = (NNODE * NNODE) / 4;
    copy4_kernel<<<(n4 + 255) / 256, 256>>>((const float4*)A_hat,
                                            (float4*)(out + (long)R_TOTAL * 12), n4);
}